// round 1
// baseline (speedup 1.0000x reference)
#include <cuda_runtime.h>
#include <cuda_bf16.h>
#include <math.h>

// ---------------- problem constants ----------------
#define Bn    4
#define Ln    1024
#define DIMn  256
#define HEADSn 8
#define DHn   64
#define DEPTHn 2
#define MLPn  512
#define INNERn 512
#define QKV3n 1536
#define ROWS  (Bn*Ln)     // 4096

// ---------------- scratch (device globals; no allocs allowed) ----------------
__device__ float g_c1[Bn*256*2*Ln];     // 8MB
__device__ float g_c2[Bn*256*Ln];       // 4MB
__device__ float g_x [ROWS*DIMn];       // 4MB
__device__ float g_h [ROWS*DIMn];       // 4MB
__device__ float g_qkv[ROWS*QKV3n];     // 25MB
__device__ float g_att[ROWS*INNERn];    // 8MB
__device__ float g_mlp[ROWS*MLPn];      // 8MB
__device__ float g_pw[ROWS];
__device__ float g_t [Bn*128];
__device__ float g_u [Bn*Ln];

// ---------------- conv1: 1->256, kernel (1,3), pad (0,1) ----------------
__global__ void conv1_kernel(const float* __restrict__ img, const float* __restrict__ w,
                             const float* __restrict__ bias, float* __restrict__ out)
{
    int idx = blockIdx.x * 256 + threadIdx.x;        // [b][c][h][l]
    if (idx >= Bn*256*2*Ln) return;
    int l  = idx & (Ln-1);
    int hh = (idx >> 10) & 1;
    int c  = (idx >> 11) & 255;
    int b  = idx >> 19;
    const float* ir = img + ((size_t)b*2 + hh)*Ln;
    float acc = bias[c];
    #pragma unroll
    for (int k = 0; k < 3; k++) {
        int ll = l + k - 1;
        if (ll >= 0 && ll < Ln) acc += ir[ll] * w[c*3 + k];
    }
    out[idx] = fmaxf(acc, 0.f);
}

// ---------------- conv2: 256->256, kernel (2,3), pad (0,1), H 2->1 ----------------
__global__ void conv2_kernel(const float* __restrict__ c1, const float* __restrict__ w,
                             const float* __restrict__ bias, float* __restrict__ out)
{
    int b  = blockIdx.y;
    int l0 = blockIdx.x * 16;
    int tid = threadIdx.x;                            // 256 = c_out
    __shared__ float patch[512][18];                  // (ci*2+h) x pos, 36KB
    for (int idx = tid; idx < 512*18; idx += 256) {
        int ch = idx / 18, p = idx % 18;
        int ci = ch >> 1, hh = ch & 1;
        int l = l0 - 1 + p;
        float v = 0.f;
        if (l >= 0 && l < Ln) v = c1[(((size_t)b*256 + ci)*2 + hh)*Ln + l];
        patch[ch][p] = v;
    }
    __syncthreads();
    float acc[16];
    float bb = bias[tid];
    #pragma unroll
    for (int t = 0; t < 16; t++) acc[t] = bb;
    const float* wr = w + (size_t)tid * 1536;         // [ci][h][k]
    for (int ci = 0; ci < 256; ci++) {
        #pragma unroll
        for (int hh = 0; hh < 2; hh++) {
            const float* wk = wr + (ci*2 + hh)*3;
            float w0 = wk[0], w1 = wk[1], w2 = wk[2];
            const float* pr = patch[ci*2 + hh];
            #pragma unroll
            for (int t = 0; t < 16; t++)
                acc[t] += w0*pr[t] + w1*pr[t+1] + w2*pr[t+2];
        }
    }
    #pragma unroll
    for (int t = 0; t < 16; t++)
        out[((size_t)b*256 + tid)*Ln + l0 + t] = fmaxf(acc[t], 0.f);
}

// ---------------- conv3: 256->DIM, kernel (1,3), pad (0,1); writes x[b,l,d] ----------------
__global__ void conv3_kernel(const float* __restrict__ c2, const float* __restrict__ w,
                             const float* __restrict__ bias, float* __restrict__ xout)
{
    int b  = blockIdx.y;
    int l0 = blockIdx.x * 16;
    int tid = threadIdx.x;                            // 256 = d
    __shared__ float patch[256][18];                  // 18KB
    for (int idx = tid; idx < 256*18; idx += 256) {
        int ci = idx / 18, p = idx % 18;
        int l = l0 - 1 + p;
        patch[ci][p] = (l >= 0 && l < Ln) ? c2[((size_t)b*256 + ci)*Ln + l] : 0.f;
    }
    __syncthreads();
    float acc[16];
    float bb = bias[tid];
    #pragma unroll
    for (int t = 0; t < 16; t++) acc[t] = bb;
    const float* wr = w + (size_t)tid * 768;
    for (int ci = 0; ci < 256; ci++) {
        float w0 = wr[ci*3+0], w1 = wr[ci*3+1], w2 = wr[ci*3+2];
        const float* pr = patch[ci];
        #pragma unroll
        for (int t = 0; t < 16; t++)
            acc[t] += w0*pr[t] + w1*pr[t+1] + w2*pr[t+2];
    }
    #pragma unroll
    for (int t = 0; t < 16; t++)
        xout[((size_t)b*Ln + l0 + t)*DIMn + tid] = fmaxf(acc[t], 0.f);
}

// ---------------- layernorm / mean pool (block per row, 256 threads) ----------------
__global__ void ln_kernel(const float* __restrict__ x, const float* __restrict__ s,
                          const float* __restrict__ b, float* __restrict__ out)
{
    int row = blockIdx.x, tid = threadIdx.x;
    __shared__ float red[256];
    float v = x[(size_t)row*DIMn + tid];
    red[tid] = v; __syncthreads();
    for (int st = 128; st > 0; st >>= 1) { if (tid < st) red[tid] += red[tid+st]; __syncthreads(); }
    float m = red[0] * (1.f/DIMn); __syncthreads();
    float d = v - m;
    red[tid] = d*d; __syncthreads();
    for (int st = 128; st > 0; st >>= 1) { if (tid < st) red[tid] += red[tid+st]; __syncthreads(); }
    float var = red[0] * (1.f/DIMn);
    out[(size_t)row*DIMn + tid] = d * rsqrtf(var + 1e-5f) * s[tid] + b[tid];
}

__global__ void meanpool_kernel(const float* __restrict__ x, float* __restrict__ w)
{
    int row = blockIdx.x, tid = threadIdx.x;
    __shared__ float red[256];
    red[tid] = x[(size_t)row*DIMn + tid]; __syncthreads();
    for (int st = 128; st > 0; st >>= 1) { if (tid < st) red[tid] += red[tid+st]; __syncthreads(); }
    if (tid == 0) w[row] = red[0] * (1.f/DIMn);
}

// ---------------- generic tiled SGEMM: C = A[MxK] @ B[KxN] (+bias)(+gelu)(+resid) ----------------
// M,N,K divisible by 64/64/16. 256 threads, 4x4 microtile.
__global__ void gemm_kernel(const float* __restrict__ A, const float* __restrict__ Bm,
                            const float* __restrict__ bias, const float* __restrict__ resid,
                            float* __restrict__ C, int M, int N, int K, int gelu)
{
    __shared__ float As[16][64];
    __shared__ float Bs[16][64];
    int tid = threadIdx.x;
    int tx = tid & 15, ty = tid >> 4;
    int bm = blockIdx.y * 64, bn = blockIdx.x * 64;
    int ar = tid >> 2, ac = (tid & 3) * 4;    // A tile load: row 0..63, k 0..12
    int br = tid >> 4, bc = (tid & 15) * 4;   // B tile load: k 0..15, col 0..60
    float acc[4][4] = {};
    for (int k0 = 0; k0 < K; k0 += 16) {
        float4 av = *(const float4*)&A[(size_t)(bm + ar)*K + k0 + ac];
        As[ac+0][ar] = av.x; As[ac+1][ar] = av.y; As[ac+2][ar] = av.z; As[ac+3][ar] = av.w;
        float4 bv = *(const float4*)&Bm[(size_t)(k0 + br)*N + bn + bc];
        *(float4*)&Bs[br][bc] = bv;
        __syncthreads();
        #pragma unroll
        for (int k = 0; k < 16; k++) {
            float a[4], b[4];
            #pragma unroll
            for (int i = 0; i < 4; i++) a[i] = As[k][ty*4 + i];
            #pragma unroll
            for (int j = 0; j < 4; j++) b[j] = Bs[k][tx*4 + j];
            #pragma unroll
            for (int i = 0; i < 4; i++)
                #pragma unroll
                for (int j = 0; j < 4; j++)
                    acc[i][j] += a[i] * b[j];
        }
        __syncthreads();
    }
    #pragma unroll
    for (int i = 0; i < 4; i++) {
        int row = bm + ty*4 + i;
        #pragma unroll
        for (int j = 0; j < 4; j++) {
            int col = bn + tx*4 + j;
            float v = acc[i][j];
            if (bias) v += bias[col];
            if (gelu) v = 0.5f * v * (1.f + erff(v * 0.70710678118f));
            if (resid) v += resid[(size_t)row*N + col];
            C[(size_t)row*N + col] = v;
        }
    }
}

// ---------------- attention: block per (b,h,i); softmax(QK*scale + pos) @ V ----------------
__global__ void attn_kernel(const float* __restrict__ qkv, const float* __restrict__ pos,
                            float* __restrict__ out)
{
    int i = blockIdx.x, h = blockIdx.y, b = blockIdx.z;
    int tid = threadIdx.x;                            // 256
    __shared__ float qs[64];
    __shared__ float s[Ln];
    __shared__ float red[256];
    __shared__ float part[4][64];
    const float* base = qkv + (size_t)b * Ln * QKV3n;
    if (tid < 64) qs[tid] = base[(size_t)i*QKV3n + h*64 + tid];
    __syncthreads();
    const float* posrow = pos + ((size_t)h*Ln + i)*Ln;
    for (int j = tid; j < Ln; j += 256) {
        const float4* kp = (const float4*)(base + (size_t)j*QKV3n + INNERn + h*64);
        float acc = 0.f;
        #pragma unroll
        for (int d4 = 0; d4 < 16; d4++) {
            float4 kv = kp[d4];
            acc += qs[d4*4+0]*kv.x + qs[d4*4+1]*kv.y + qs[d4*4+2]*kv.z + qs[d4*4+3]*kv.w;
        }
        s[j] = acc * 0.125f + posrow[j];
    }
    __syncthreads();
    // max
    float lm = -1e30f;
    for (int j = tid; j < Ln; j += 256) lm = fmaxf(lm, s[j]);
    red[tid] = lm; __syncthreads();
    for (int st = 128; st > 0; st >>= 1) { if (tid < st) red[tid] = fmaxf(red[tid], red[tid+st]); __syncthreads(); }
    float mx = red[0]; __syncthreads();
    // exp + sum
    float ls = 0.f;
    for (int j = tid; j < Ln; j += 256) { float e = expf(s[j] - mx); s[j] = e; ls += e; }
    red[tid] = ls; __syncthreads();
    for (int st = 128; st > 0; st >>= 1) { if (tid < st) red[tid] += red[tid+st]; __syncthreads(); }
    float inv = 1.f / red[0];
    __syncthreads();
    // PV
    int d = tid & 63, g = tid >> 6;
    float acc = 0.f;
    const float* vb = base + 2*INNERn + h*64 + d;
    int j0 = g * 256;
    for (int j = j0; j < j0 + 256; j++) acc += s[j] * vb[(size_t)j*QKV3n];
    part[g][d] = acc; __syncthreads();
    if (tid < 64) {
        float o = (part[0][tid] + part[1][tid] + part[2][tid] + part[3][tid]) * inv;
        out[((size_t)b*Ln + i)*INNERn + h*64 + tid] = o;
    }
}

// ---------------- SE pool tail ----------------
__global__ void se1_kernel(const float* __restrict__ wv, const float* __restrict__ w1,
                           const float* __restrict__ b1, float* __restrict__ t)
{
    int tid = threadIdx.x;                            // 512
    int b = tid >> 7, j = tid & 127;
    float acc = b1[j];
    for (int l = 0; l < Ln; l++) acc += wv[b*Ln + l] * w1[l*128 + j];
    t[tid] = fmaxf(acc, 0.f);
}

__global__ void se2_kernel(const float* __restrict__ t, const float* __restrict__ w2,
                           const float* __restrict__ b2, float* __restrict__ u)
{
    int idx = blockIdx.x * 256 + threadIdx.x;         // 4096
    int b = idx >> 10, l = idx & (Ln-1);
    float acc = b2[l];
    #pragma unroll
    for (int j = 0; j < 128; j++) acc += t[b*128 + j] * w2[j*Ln + l];
    u[idx] = 1.f / (1.f + expf(-acc));
}

__global__ void pool_out_kernel(const float* __restrict__ u, const float* __restrict__ x,
                                float* __restrict__ out)
{
    int b = blockIdx.x, d = threadIdx.x;              // 4 x 256
    float acc = 0.f;
    for (int l = 0; l < Ln; l++) acc += u[b*Ln + l] * x[((size_t)b*Ln + l)*DIMn + d];
    out[b*DIMn + d] = acc;
}

// ---------------- host launch ----------------
extern "C" void kernel_launch(void* const* d_in, const int* in_sizes, int n_in,
                              void* d_out, int out_size)
{
    const float* img     = (const float*)d_in[0];
    const float* conv1_w = (const float*)d_in[1];
    const float* conv1_b = (const float*)d_in[2];
    const float* conv2_w = (const float*)d_in[3];
    const float* conv2_b = (const float*)d_in[4];
    const float* conv3_w = (const float*)d_in[5];
    const float* conv3_b = (const float*)d_in[6];
    const float* ln1_s   = (const float*)d_in[7];
    const float* ln1_b   = (const float*)d_in[8];
    const float* qkv_w   = (const float*)d_in[9];
    const float* pos     = (const float*)d_in[10];
    const float* out_w   = (const float*)d_in[11];
    const float* out_b   = (const float*)d_in[12];
    const float* ln2_s   = (const float*)d_in[13];
    const float* ln2_b   = (const float*)d_in[14];
    const float* ff_w1   = (const float*)d_in[15];
    const float* ff_b1   = (const float*)d_in[16];
    const float* ff_w2   = (const float*)d_in[17];
    const float* ff_b2   = (const float*)d_in[18];
    const float* se_w1   = (const float*)d_in[19];
    const float* se_b1   = (const float*)d_in[20];
    const float* se_w2   = (const float*)d_in[21];
    const float* se_b2   = (const float*)d_in[22];
    float* out = (float*)d_out;

    float *c1, *c2, *x, *h, *qkv, *att, *mlp, *pw, *t, *u;
    cudaGetSymbolAddress((void**)&c1,  g_c1);
    cudaGetSymbolAddress((void**)&c2,  g_c2);
    cudaGetSymbolAddress((void**)&x,   g_x);
    cudaGetSymbolAddress((void**)&h,   g_h);
    cudaGetSymbolAddress((void**)&qkv, g_qkv);
    cudaGetSymbolAddress((void**)&att, g_att);
    cudaGetSymbolAddress((void**)&mlp, g_mlp);
    cudaGetSymbolAddress((void**)&pw,  g_pw);
    cudaGetSymbolAddress((void**)&t,   g_t);
    cudaGetSymbolAddress((void**)&u,   g_u);

    // conv patch embed
    conv1_kernel<<<(Bn*256*2*Ln + 255)/256, 256>>>(img, conv1_w, conv1_b, c1);
    conv2_kernel<<<dim3(Ln/16, Bn), 256>>>(c1, conv2_w, conv2_b, c2);
    conv3_kernel<<<dim3(Ln/16, Bn), 256>>>(c2, conv3_w, conv3_b, x);

    for (int lyr = 0; lyr < DEPTHn; lyr++) {
        // attention block
        ln_kernel<<<ROWS, 256>>>(x, ln1_s + lyr*DIMn, ln1_b + lyr*DIMn, h);
        gemm_kernel<<<dim3(QKV3n/64, ROWS/64), 256>>>(h, qkv_w + (size_t)lyr*DIMn*QKV3n,
                                                      nullptr, nullptr, qkv,
                                                      ROWS, QKV3n, DIMn, 0);
        attn_kernel<<<dim3(Ln, HEADSn, Bn), 256>>>(qkv, pos + (size_t)lyr*HEADSn*Ln*Ln, att);
        gemm_kernel<<<dim3(DIMn/64, ROWS/64), 256>>>(att, out_w + (size_t)lyr*INNERn*DIMn,
                                                     out_b + lyr*DIMn, x, x,
                                                     ROWS, DIMn, INNERn, 0);
        // MLP block
        ln_kernel<<<ROWS, 256>>>(x, ln2_s + lyr*DIMn, ln2_b + lyr*DIMn, h);
        gemm_kernel<<<dim3(MLPn/64, ROWS/64), 256>>>(h, ff_w1 + (size_t)lyr*DIMn*MLPn,
                                                     ff_b1 + lyr*MLPn, nullptr, mlp,
                                                     ROWS, MLPn, DIMn, 1);
        gemm_kernel<<<dim3(DIMn/64, ROWS/64), 256>>>(mlp, ff_w2 + (size_t)lyr*MLPn*DIMn,
                                                     ff_b2 + lyr*DIMn, x, x,
                                                     ROWS, DIMn, MLPn, 0);
    }

    // SE attention pool
    meanpool_kernel<<<ROWS, 256>>>(x, pw);
    se1_kernel<<<1, 512>>>(pw, se_w1, se_b1, t);
    se2_kernel<<<(Bn*Ln)/256, 256>>>(t, se_w2, se_b2, u);
    pool_out_kernel<<<Bn, 256>>>(u, x, out);
}

// round 2
// speedup vs baseline: 3.0331x; 3.0331x over previous
#include <cuda_runtime.h>
#include <cuda_bf16.h>
#include <math.h>

// ---------------- problem constants ----------------
#define Bn    4
#define Ln    1024
#define DIMn  256
#define HEADSn 8
#define DHn   64
#define DEPTHn 2
#define MLPn  512
#define INNERn 512
#define QKV3n 1536
#define ROWS  (Bn*Ln)     // 4096

// ---------------- scratch (device globals; no allocs allowed) ----------------
__device__ float g_c1[Bn*256*2*Ln];     // 8MB
__device__ float g_c2[Bn*256*Ln];       // 4MB
__device__ float g_x [ROWS*DIMn];       // 4MB
__device__ float g_h [ROWS*DIMn];       // 4MB
__device__ float g_qkv[ROWS*QKV3n];     // 25MB
__device__ float g_att[ROWS*INNERn];    // 8MB
__device__ float g_mlp[ROWS*MLPn];      // 8MB
__device__ float g_pw[ROWS];
__device__ float g_t [Bn*128];
__device__ float g_u [Bn*Ln];

// ---------------- conv1: 1->256, kernel (1,3), pad (0,1) ----------------
__global__ void conv1_kernel(const float* __restrict__ img, const float* __restrict__ w,
                             const float* __restrict__ bias, float* __restrict__ out)
{
    int idx = blockIdx.x * 256 + threadIdx.x;        // [b][c][h][l]
    if (idx >= Bn*256*2*Ln) return;
    int l  = idx & (Ln-1);
    int hh = (idx >> 10) & 1;
    int c  = (idx >> 11) & 255;
    int b  = idx >> 19;
    const float* ir = img + ((size_t)b*2 + hh)*Ln;
    float acc = bias[c];
    #pragma unroll
    for (int k = 0; k < 3; k++) {
        int ll = l + k - 1;
        if (ll >= 0 && ll < Ln) acc += ir[ll] * w[c*3 + k];
    }
    out[idx] = fmaxf(acc, 0.f);
}

// ---------------- conv2: 256->256, kernel (2,3), pad (0,1), H 2->1 ----------------
__global__ void conv2_kernel(const float* __restrict__ c1, const float* __restrict__ w,
                             const float* __restrict__ bias, float* __restrict__ out)
{
    int b  = blockIdx.y;
    int l0 = blockIdx.x * 16;
    int tid = threadIdx.x;                            // 256 = c_out
    __shared__ float patch[512][18];                  // (ci*2+h) x pos, 36KB
    for (int idx = tid; idx < 512*18; idx += 256) {
        int ch = idx / 18, p = idx % 18;
        int ci = ch >> 1, hh = ch & 1;
        int l = l0 - 1 + p;
        float v = 0.f;
        if (l >= 0 && l < Ln) v = c1[(((size_t)b*256 + ci)*2 + hh)*Ln + l];
        patch[ch][p] = v;
    }
    __syncthreads();
    float acc[16];
    float bb = bias[tid];
    #pragma unroll
    for (int t = 0; t < 16; t++) acc[t] = bb;
    const float* wr = w + (size_t)tid * 1536;         // [ci][h][k]
    for (int ci = 0; ci < 256; ci++) {
        #pragma unroll
        for (int hh = 0; hh < 2; hh++) {
            const float* wk = wr + (ci*2 + hh)*3;
            float w0 = wk[0], w1 = wk[1], w2 = wk[2];
            const float* pr = patch[ci*2 + hh];
            #pragma unroll
            for (int t = 0; t < 16; t++)
                acc[t] += w0*pr[t] + w1*pr[t+1] + w2*pr[t+2];
        }
    }
    #pragma unroll
    for (int t = 0; t < 16; t++)
        out[((size_t)b*256 + tid)*Ln + l0 + t] = fmaxf(acc[t], 0.f);
}

// ---------------- conv3: 256->DIM, kernel (1,3), pad (0,1); writes x[b,l,d] ----------------
__global__ void conv3_kernel(const float* __restrict__ c2, const float* __restrict__ w,
                             const float* __restrict__ bias, float* __restrict__ xout)
{
    int b  = blockIdx.y;
    int l0 = blockIdx.x * 16;
    int tid = threadIdx.x;                            // 256 = d
    __shared__ float patch[256][18];                  // 18KB
    for (int idx = tid; idx < 256*18; idx += 256) {
        int ci = idx / 18, p = idx % 18;
        int l = l0 - 1 + p;
        patch[ci][p] = (l >= 0 && l < Ln) ? c2[((size_t)b*256 + ci)*Ln + l] : 0.f;
    }
    __syncthreads();
    float acc[16];
    float bb = bias[tid];
    #pragma unroll
    for (int t = 0; t < 16; t++) acc[t] = bb;
    const float* wr = w + (size_t)tid * 768;
    for (int ci = 0; ci < 256; ci++) {
        float w0 = wr[ci*3+0], w1 = wr[ci*3+1], w2 = wr[ci*3+2];
        const float* pr = patch[ci];
        #pragma unroll
        for (int t = 0; t < 16; t++)
            acc[t] += w0*pr[t] + w1*pr[t+1] + w2*pr[t+2];
    }
    #pragma unroll
    for (int t = 0; t < 16; t++)
        xout[((size_t)b*Ln + l0 + t)*DIMn + tid] = fmaxf(acc[t], 0.f);
}

// ---------------- layernorm / mean pool (block per row, 256 threads) ----------------
__global__ void ln_kernel(const float* __restrict__ x, const float* __restrict__ s,
                          const float* __restrict__ b, float* __restrict__ out)
{
    int row = blockIdx.x, tid = threadIdx.x;
    __shared__ float red[256];
    float v = x[(size_t)row*DIMn + tid];
    red[tid] = v; __syncthreads();
    for (int st = 128; st > 0; st >>= 1) { if (tid < st) red[tid] += red[tid+st]; __syncthreads(); }
    float m = red[0] * (1.f/DIMn); __syncthreads();
    float d = v - m;
    red[tid] = d*d; __syncthreads();
    for (int st = 128; st > 0; st >>= 1) { if (tid < st) red[tid] += red[tid+st]; __syncthreads(); }
    float var = red[0] * (1.f/DIMn);
    out[(size_t)row*DIMn + tid] = d * rsqrtf(var + 1e-5f) * s[tid] + b[tid];
}

__global__ void meanpool_kernel(const float* __restrict__ x, float* __restrict__ w)
{
    int row = blockIdx.x, tid = threadIdx.x;
    __shared__ float red[256];
    red[tid] = x[(size_t)row*DIMn + tid]; __syncthreads();
    for (int st = 128; st > 0; st >>= 1) { if (tid < st) red[tid] += red[tid+st]; __syncthreads(); }
    if (tid == 0) w[row] = red[0] * (1.f/DIMn);
}

// ---------------- tiled SGEMM: C = A[MxK] @ B[KxN] (+bias)(+gelu)(+resid) ----------------
// BN=128 fixed, BM = 16*TM, 256 threads, TMx8 microtile, k-tile 16.
template<int BM, int TM, bool GELU, bool HASB, bool HASR>
__global__ void gemm_kernel(const float* __restrict__ A, const float* __restrict__ Bm,
                            const float* __restrict__ bias, const float* __restrict__ resid,
                            float* __restrict__ C, int M, int N, int K)
{
    __shared__ float As[16][BM + 4];
    __shared__ float Bs[16][132];
    int tid = threadIdx.x;
    int ty = tid >> 4, tx = tid & 15;
    int bm = blockIdx.y * BM, bn = blockIdx.x * 128;
    float acc[TM][8];
    #pragma unroll
    for (int i = 0; i < TM; i++)
        #pragma unroll
        for (int j = 0; j < 8; j++) acc[i][j] = 0.f;

    for (int k0 = 0; k0 < K; k0 += 16) {
        #pragma unroll
        for (int v = 0; v < BM/64; v++) {
            int f = tid + 256*v;
            int r = f >> 2, kc = (f & 3) * 4;
            float4 av = *(const float4*)&A[(size_t)(bm + r)*K + k0 + kc];
            As[kc+0][r] = av.x; As[kc+1][r] = av.y; As[kc+2][r] = av.z; As[kc+3][r] = av.w;
        }
        #pragma unroll
        for (int v = 0; v < 2; v++) {
            int f = tid + 256*v;
            int kr = f >> 5, c4 = (f & 31) * 4;
            *(float4*)&Bs[kr][c4] = *(const float4*)&Bm[(size_t)(k0 + kr)*N + bn + c4];
        }
        __syncthreads();
        #pragma unroll
        for (int k = 0; k < 16; k++) {
            float a[TM], bv[8];
            #pragma unroll
            for (int i = 0; i < TM/4; i++)
                *(float4*)&a[i*4] = *(float4*)&As[k][ty*TM + i*4];
            *(float4*)&bv[0] = *(float4*)&Bs[k][tx*8];
            *(float4*)&bv[4] = *(float4*)&Bs[k][tx*8 + 4];
            #pragma unroll
            for (int i = 0; i < TM; i++)
                #pragma unroll
                for (int j = 0; j < 8; j++)
                    acc[i][j] += a[i] * bv[j];
        }
        __syncthreads();
    }
    #pragma unroll
    for (int i = 0; i < TM; i++) {
        int row = bm + ty*TM + i;
        #pragma unroll
        for (int j = 0; j < 8; j++) {
            int col = bn + tx*8 + j;
            float v = acc[i][j];
            if (HASB) v += bias[col];
            if (GELU) v = 0.5f * v * (1.f + erff(v * 0.70710678118f));
            if (HASR) v += resid[(size_t)row*N + col];
            C[(size_t)row*N + col] = v;
        }
    }
}

// ---------------- flash attention: block = (b, h, 64 q-rows); j-tiles of 64 ----------------
__global__ __launch_bounds__(256, 2)
void attn_kernel(const float* __restrict__ qkv, const float* __restrict__ pos,
                 float* __restrict__ out)
{
    extern __shared__ float sm[];
    float (*Qs)[68] = (float(*)[68])sm;              // [k][i]
    float (*Ks)[68] = (float(*)[68])(sm + 64*68);    // [k][j]
    float (*Vs)[68] = (float(*)[68])(sm + 2*64*68);  // [j][d]
    float (*Ps)[68] = (float(*)[68])(sm + 3*64*68);  // [j][i]

    int bq = blockIdx.x, h = blockIdx.y, b = blockIdx.z;
    int i0 = bq * 64;
    int tid = threadIdx.x;
    int ty = tid >> 4, tx = tid & 15;      // rows ty*4.., cols tx*4..
    const float* base = qkv + (size_t)b * Ln * QKV3n;

    // load Q tile transposed into Qs[k][i]
    #pragma unroll
    for (int v = 0; v < 4; v++) {
        int f = tid + 256*v;
        int r = f >> 4, kc = (f & 15) * 4;
        float4 qv = *(const float4*)&base[(size_t)(i0 + r)*QKV3n + h*64 + kc];
        Qs[kc+0][r] = qv.x; Qs[kc+1][r] = qv.y; Qs[kc+2][r] = qv.z; Qs[kc+3][r] = qv.w;
    }

    float m[4], l[4], o[4][4];
    #pragma unroll
    for (int i = 0; i < 4; i++) {
        m[i] = -1e30f; l[i] = 0.f;
        #pragma unroll
        for (int d = 0; d < 4; d++) o[i][d] = 0.f;
    }

    const float* posb = pos + ((size_t)h*Ln + i0)*Ln;

    for (int jt = 0; jt < 16; jt++) {
        int j0 = jt * 64;
        __syncthreads();   // prev PV done (and Q tile ready on first iter)
        // load K tile transposed, V tile direct
        #pragma unroll
        for (int v = 0; v < 4; v++) {
            int f = tid + 256*v;
            int r = f >> 4, kc = (f & 15) * 4;
            float4 kv = *(const float4*)&base[(size_t)(j0 + r)*QKV3n + INNERn + h*64 + kc];
            Ks[kc+0][r] = kv.x; Ks[kc+1][r] = kv.y; Ks[kc+2][r] = kv.z; Ks[kc+3][r] = kv.w;
            float4 vv = *(const float4*)&base[(size_t)(j0 + r)*QKV3n + 2*INNERn + h*64 + kc];
            *(float4*)&Vs[r][kc] = vv;
        }
        // prefetch pos bias for this tile
        float4 pv[4];
        #pragma unroll
        for (int i = 0; i < 4; i++)
            pv[i] = *(const float4*)&posb[(size_t)(ty*4 + i)*Ln + j0 + tx*4];
        __syncthreads();

        // S = Q @ K^T  (64x64x64)
        float s[4][4];
        #pragma unroll
        for (int i = 0; i < 4; i++)
            #pragma unroll
            for (int j = 0; j < 4; j++) s[i][j] = 0.f;
        #pragma unroll 8
        for (int k = 0; k < 64; k++) {
            float a[4], bb[4];
            *(float4*)a  = *(float4*)&Qs[k][ty*4];
            *(float4*)bb = *(float4*)&Ks[k][tx*4];
            #pragma unroll
            for (int i = 0; i < 4; i++)
                #pragma unroll
                for (int j = 0; j < 4; j++)
                    s[i][j] += a[i] * bb[j];
        }
        // scale + pos bias
        #pragma unroll
        for (int i = 0; i < 4; i++) {
            s[i][0] = s[i][0]*0.125f + pv[i].x;
            s[i][1] = s[i][1]*0.125f + pv[i].y;
            s[i][2] = s[i][2]*0.125f + pv[i].z;
            s[i][3] = s[i][3]*0.125f + pv[i].w;
        }
        // online softmax stats per row (reduce across tx = low 4 lane bits)
        #pragma unroll
        for (int i = 0; i < 4; i++) {
            float tm = fmaxf(fmaxf(s[i][0], s[i][1]), fmaxf(s[i][2], s[i][3]));
            #pragma unroll
            for (int off = 1; off < 16; off <<= 1)
                tm = fmaxf(tm, __shfl_xor_sync(0xffffffffu, tm, off));
            float mn = fmaxf(m[i], tm);
            float corr = expf(m[i] - mn);
            float e0 = expf(s[i][0] - mn), e1 = expf(s[i][1] - mn);
            float e2 = expf(s[i][2] - mn), e3 = expf(s[i][3] - mn);
            s[i][0] = e0; s[i][1] = e1; s[i][2] = e2; s[i][3] = e3;
            float ts = e0 + e1 + e2 + e3;
            #pragma unroll
            for (int off = 1; off < 16; off <<= 1)
                ts += __shfl_xor_sync(0xffffffffu, ts, off);
            l[i] = l[i]*corr + ts;
            m[i] = mn;
            #pragma unroll
            for (int d = 0; d < 4; d++) o[i][d] *= corr;
        }
        // write P transposed: Ps[j][i]
        #pragma unroll
        for (int j = 0; j < 4; j++)
            #pragma unroll
            for (int i = 0; i < 4; i++)
                Ps[tx*4 + j][ty*4 + i] = s[i][j];
        __syncthreads();
        // O += P @ V  (64x64x64)
        #pragma unroll 8
        for (int jj = 0; jj < 64; jj++) {
            float a[4], bb[4];
            *(float4*)a  = *(float4*)&Ps[jj][ty*4];
            *(float4*)bb = *(float4*)&Vs[jj][tx*4];
            #pragma unroll
            for (int i = 0; i < 4; i++)
                #pragma unroll
                for (int d = 0; d < 4; d++)
                    o[i][d] += a[i] * bb[d];
        }
    }
    // normalize + write
    #pragma unroll
    for (int i = 0; i < 4; i++) {
        float inv = 1.f / l[i];
        #pragma unroll
        for (int d = 0; d < 4; d++)
            out[((size_t)b*Ln + i0 + ty*4 + i)*INNERn + h*64 + tx*4 + d] = o[i][d] * inv;
    }
}

// ---------------- SE pool tail ----------------
__global__ void se1_kernel(const float* __restrict__ wv, const float* __restrict__ w1,
                           const float* __restrict__ b1, float* __restrict__ t)
{
    int tid = threadIdx.x;                            // 512
    int b = tid >> 7, j = tid & 127;
    float acc = b1[j];
    for (int l = 0; l < Ln; l++) acc += wv[b*Ln + l] * w1[l*128 + j];
    t[tid] = fmaxf(acc, 0.f);
}

__global__ void se2_kernel(const float* __restrict__ t, const float* __restrict__ w2,
                           const float* __restrict__ b2, float* __restrict__ u)
{
    int idx = blockIdx.x * 256 + threadIdx.x;         // 4096
    int b = idx >> 10, l = idx & (Ln-1);
    float acc = b2[l];
    #pragma unroll
    for (int j = 0; j < 128; j++) acc += t[b*128 + j] * w2[j*Ln + l];
    u[idx] = 1.f / (1.f + expf(-acc));
}

__global__ void pool_out_kernel(const float* __restrict__ u, const float* __restrict__ x,
                                float* __restrict__ out)
{
    int b = blockIdx.x, d = threadIdx.x;              // 4 x 256
    float acc = 0.f;
    for (int l = 0; l < Ln; l++) acc += u[b*Ln + l] * x[((size_t)b*Ln + l)*DIMn + d];
    out[b*DIMn + d] = acc;
}

// ---------------- host launch ----------------
extern "C" void kernel_launch(void* const* d_in, const int* in_sizes, int n_in,
                              void* d_out, int out_size)
{
    const float* img     = (const float*)d_in[0];
    const float* conv1_w = (const float*)d_in[1];
    const float* conv1_b = (const float*)d_in[2];
    const float* conv2_w = (const float*)d_in[3];
    const float* conv2_b = (const float*)d_in[4];
    const float* conv3_w = (const float*)d_in[5];
    const float* conv3_b = (const float*)d_in[6];
    const float* ln1_s   = (const float*)d_in[7];
    const float* ln1_b   = (const float*)d_in[8];
    const float* qkv_w   = (const float*)d_in[9];
    const float* pos     = (const float*)d_in[10];
    const float* out_w   = (const float*)d_in[11];
    const float* out_b   = (const float*)d_in[12];
    const float* ln2_s   = (const float*)d_in[13];
    const float* ln2_b   = (const float*)d_in[14];
    const float* ff_w1   = (const float*)d_in[15];
    const float* ff_b1   = (const float*)d_in[16];
    const float* ff_w2   = (const float*)d_in[17];
    const float* ff_b2   = (const float*)d_in[18];
    const float* se_w1   = (const float*)d_in[19];
    const float* se_b1   = (const float*)d_in[20];
    const float* se_w2   = (const float*)d_in[21];
    const float* se_b2   = (const float*)d_in[22];
    float* out = (float*)d_out;

    float *c1, *c2, *x, *h, *qkv, *att, *mlp, *pw, *t, *u;
    cudaGetSymbolAddress((void**)&c1,  g_c1);
    cudaGetSymbolAddress((void**)&c2,  g_c2);
    cudaGetSymbolAddress((void**)&x,   g_x);
    cudaGetSymbolAddress((void**)&h,   g_h);
    cudaGetSymbolAddress((void**)&qkv, g_qkv);
    cudaGetSymbolAddress((void**)&att, g_att);
    cudaGetSymbolAddress((void**)&mlp, g_mlp);
    cudaGetSymbolAddress((void**)&pw,  g_pw);
    cudaGetSymbolAddress((void**)&t,   g_t);
    cudaGetSymbolAddress((void**)&u,   g_u);

    const int ATTN_SMEM = 4 * 64 * 68 * 4;  // 69632 bytes
    cudaFuncSetAttribute(attn_kernel, cudaFuncAttributeMaxDynamicSharedMemorySize, ATTN_SMEM);

    // conv patch embed
    conv1_kernel<<<(Bn*256*2*Ln + 255)/256, 256>>>(img, conv1_w, conv1_b, c1);
    conv2_kernel<<<dim3(Ln/16, Bn), 256>>>(c1, conv2_w, conv2_b, c2);
    conv3_kernel<<<dim3(Ln/16, Bn), 256>>>(c2, conv3_w, conv3_b, x);

    for (int lyr = 0; lyr < DEPTHn; lyr++) {
        // attention block
        ln_kernel<<<ROWS, 256>>>(x, ln1_s + lyr*DIMn, ln1_b + lyr*DIMn, h);
        gemm_kernel<128,8,false,false,false><<<dim3(QKV3n/128, ROWS/128), 256>>>(
            h, qkv_w + (size_t)lyr*DIMn*QKV3n, nullptr, nullptr, qkv, ROWS, QKV3n, DIMn);
        attn_kernel<<<dim3(Ln/64, HEADSn, Bn), 256, ATTN_SMEM>>>(
            qkv, pos + (size_t)lyr*HEADSn*Ln*Ln, att);
        gemm_kernel<64,4,false,true,true><<<dim3(DIMn/128, ROWS/64), 256>>>(
            att, out_w + (size_t)lyr*INNERn*DIMn, out_b + lyr*DIMn, x, x, ROWS, DIMn, INNERn);
        // MLP block
        ln_kernel<<<ROWS, 256>>>(x, ln2_s + lyr*DIMn, ln2_b + lyr*DIMn, h);
        gemm_kernel<128,8,true,true,false><<<dim3(MLPn/128, ROWS/128), 256>>>(
            h, ff_w1 + (size_t)lyr*DIMn*MLPn, ff_b1 + lyr*MLPn, nullptr, mlp, ROWS, MLPn, DIMn);
        gemm_kernel<64,4,false,true,true><<<dim3(DIMn/128, ROWS/64), 256>>>(
            mlp, ff_w2 + (size_t)lyr*MLPn*DIMn, ff_b2 + lyr*DIMn, x, x, ROWS, DIMn, MLPn);
    }

    // SE attention pool
    meanpool_kernel<<<ROWS, 256>>>(x, pw);
    se1_kernel<<<1, 512>>>(pw, se_w1, se_b1, t);
    se2_kernel<<<(Bn*Ln)/256, 256>>>(t, se_w2, se_b2, u);
    pool_out_kernel<<<Bn, 256>>>(u, x, out);
}

// round 3
// speedup vs baseline: 3.7328x; 1.2307x over previous
#include <cuda_runtime.h>
#include <cuda_bf16.h>
#include <math.h>

// ---------------- problem constants ----------------
#define Bn    4
#define Ln    1024
#define DIMn  256
#define HEADSn 8
#define DHn   64
#define DEPTHn 2
#define MLPn  512
#define INNERn 512
#define QKV3n 1536
#define ROWS  (Bn*Ln)     // 4096

// ---------------- scratch (device globals; no allocs allowed) ----------------
__device__ float g_c1[Bn*256*2*Ln];     // 8MB
__device__ float g_c2[Bn*256*Ln];       // 4MB
__device__ float g_x [ROWS*DIMn];       // 4MB
__device__ float g_h [ROWS*DIMn];       // 4MB
__device__ float g_qkv[ROWS*QKV3n];     // 25MB
__device__ float g_att[ROWS*INNERn];    // 8MB
__device__ float g_mlp[ROWS*MLPn];      // 8MB
__device__ float g_pw[ROWS];
__device__ float g_t [Bn*128];
__device__ float g_u [Bn*Ln];

// ---------------- helpers: tf32 mma + packed f32x2 ----------------
__device__ __forceinline__ unsigned tf32_of(float f) {
    unsigned u; asm("cvt.rna.tf32.f32 %0, %1;" : "=r"(u) : "f"(f)); return u;
}
__device__ __forceinline__ void mma_tf32(float* c, const unsigned* a, const unsigned* b) {
    asm volatile("mma.sync.aligned.m16n8k8.row.col.f32.tf32.tf32.f32 "
        "{%0,%1,%2,%3}, {%4,%5,%6,%7}, {%8,%9}, {%0,%1,%2,%3};"
        : "+f"(c[0]), "+f"(c[1]), "+f"(c[2]), "+f"(c[3])
        : "r"(a[0]), "r"(a[1]), "r"(a[2]), "r"(a[3]), "r"(b[0]), "r"(b[1]));
}
__device__ __forceinline__ unsigned long long pk(float x, float y) {
    unsigned long long r;
    asm("mov.b64 %0, {%1, %2};" : "=l"(r) : "f"(x), "f"(y));
    return r;
}
__device__ __forceinline__ float2 upk(unsigned long long v) {
    float2 r; asm("mov.b64 {%0, %1}, %2;" : "=f"(r.x), "=f"(r.y) : "l"(v)); return r;
}
__device__ __forceinline__ void fma2(unsigned long long& c, unsigned long long a, unsigned long long b) {
    asm("fma.rn.f32x2 %0, %1, %2, %3;" : "=l"(c) : "l"(a), "l"(b), "l"(c));
}
__device__ __forceinline__ unsigned long long mul2(unsigned long long a, unsigned long long b) {
    unsigned long long r;
    asm("mul.rn.f32x2 %0, %1, %2;" : "=l"(r) : "l"(a), "l"(b));
    return r;
}

// ---------------- conv1: 1->256, kernel (1,3), pad (0,1) ----------------
__global__ void conv1_kernel(const float* __restrict__ img, const float* __restrict__ w,
                             const float* __restrict__ bias, float* __restrict__ out)
{
    int idx = blockIdx.x * 256 + threadIdx.x;        // [b][c][h][l]
    if (idx >= Bn*256*2*Ln) return;
    int l  = idx & (Ln-1);
    int hh = (idx >> 10) & 1;
    int c  = (idx >> 11) & 255;
    int b  = idx >> 19;
    const float* ir = img + ((size_t)b*2 + hh)*Ln;
    float acc = bias[c];
    #pragma unroll
    for (int k = 0; k < 3; k++) {
        int ll = l + k - 1;
        if (ll >= 0 && ll < Ln) acc += ir[ll] * w[c*3 + k];
    }
    out[idx] = fmaxf(acc, 0.f);
}

// ---------------- conv2: 256->256, kernel (2,3), pad (0,1), H 2->1 ----------------
__global__ void conv2_kernel(const float* __restrict__ c1, const float* __restrict__ w,
                             const float* __restrict__ bias, float* __restrict__ out)
{
    int b  = blockIdx.y;
    int l0 = blockIdx.x * 16;
    int tid = threadIdx.x;                            // 256 = c_out
    __shared__ float patch[512][18];                  // (ci*2+h) x pos, 36KB
    for (int idx = tid; idx < 512*18; idx += 256) {
        int ch = idx / 18, p = idx % 18;
        int ci = ch >> 1, hh = ch & 1;
        int l = l0 - 1 + p;
        float v = 0.f;
        if (l >= 0 && l < Ln) v = c1[(((size_t)b*256 + ci)*2 + hh)*Ln + l];
        patch[ch][p] = v;
    }
    __syncthreads();
    float acc[16];
    float bb = bias[tid];
    #pragma unroll
    for (int t = 0; t < 16; t++) acc[t] = bb;
    const float* wr = w + (size_t)tid * 1536;         // [ci][h][k]
    for (int ci = 0; ci < 256; ci++) {
        #pragma unroll
        for (int hh = 0; hh < 2; hh++) {
            const float* wk = wr + (ci*2 + hh)*3;
            float w0 = wk[0], w1 = wk[1], w2 = wk[2];
            const float* pr = patch[ci*2 + hh];
            #pragma unroll
            for (int t = 0; t < 16; t++)
                acc[t] += w0*pr[t] + w1*pr[t+1] + w2*pr[t+2];
        }
    }
    #pragma unroll
    for (int t = 0; t < 16; t++)
        out[((size_t)b*256 + tid)*Ln + l0 + t] = fmaxf(acc[t], 0.f);
}

// ---------------- conv3: 256->DIM, kernel (1,3), pad (0,1); writes x[b,l,d] ----------------
__global__ void conv3_kernel(const float* __restrict__ c2, const float* __restrict__ w,
                             const float* __restrict__ bias, float* __restrict__ xout)
{
    int b  = blockIdx.y;
    int l0 = blockIdx.x * 16;
    int tid = threadIdx.x;                            // 256 = d
    __shared__ float patch[256][18];                  // 18KB
    for (int idx = tid; idx < 256*18; idx += 256) {
        int ci = idx / 18, p = idx % 18;
        int l = l0 - 1 + p;
        patch[ci][p] = (l >= 0 && l < Ln) ? c2[((size_t)b*256 + ci)*Ln + l] : 0.f;
    }
    __syncthreads();
    float acc[16];
    float bb = bias[tid];
    #pragma unroll
    for (int t = 0; t < 16; t++) acc[t] = bb;
    const float* wr = w + (size_t)tid * 768;
    for (int ci = 0; ci < 256; ci++) {
        float w0 = wr[ci*3+0], w1 = wr[ci*3+1], w2 = wr[ci*3+2];
        const float* pr = patch[ci];
        #pragma unroll
        for (int t = 0; t < 16; t++)
            acc[t] += w0*pr[t] + w1*pr[t+1] + w2*pr[t+2];
    }
    #pragma unroll
    for (int t = 0; t < 16; t++)
        xout[((size_t)b*Ln + l0 + t)*DIMn + tid] = fmaxf(acc[t], 0.f);
}

// ---------------- layernorm / mean pool (block per row, 256 threads) ----------------
__global__ void ln_kernel(const float* __restrict__ x, const float* __restrict__ s,
                          const float* __restrict__ b, float* __restrict__ out)
{
    int row = blockIdx.x, tid = threadIdx.x;
    __shared__ float red[256];
    float v = x[(size_t)row*DIMn + tid];
    red[tid] = v; __syncthreads();
    for (int st = 128; st > 0; st >>= 1) { if (tid < st) red[tid] += red[tid+st]; __syncthreads(); }
    float m = red[0] * (1.f/DIMn); __syncthreads();
    float d = v - m;
    red[tid] = d*d; __syncthreads();
    for (int st = 128; st > 0; st >>= 1) { if (tid < st) red[tid] += red[tid+st]; __syncthreads(); }
    float var = red[0] * (1.f/DIMn);
    out[(size_t)row*DIMn + tid] = d * rsqrtf(var + 1e-5f) * s[tid] + b[tid];
}

__global__ void meanpool_kernel(const float* __restrict__ x, float* __restrict__ w)
{
    int row = blockIdx.x, tid = threadIdx.x;
    __shared__ float red[256];
    red[tid] = x[(size_t)row*DIMn + tid]; __syncthreads();
    for (int st = 128; st > 0; st >>= 1) { if (tid < st) red[tid] += red[tid+st]; __syncthreads(); }
    if (tid == 0) w[row] = red[0] * (1.f/DIMn);
}

// ---------------- tf32 tensor-core GEMM: C = A[MxK] @ B[KxN] (+bias)(+gelu)(+resid) ----------------
// BN=128 fixed. 256 threads = 8 warps. BM=128: warp grid 4x2 (warp tile 32x64).
// BM=64: warp grid 2x4 (warp tile 32x32). K-tile 32, mma m16n8k8 tf32.
template<int BM, bool GELU, bool HASB, bool HASR>
__global__ __launch_bounds__(256)
void gemm_tf32_kernel(const float* __restrict__ A, const float* __restrict__ Bm,
                      const float* __restrict__ bias, const float* __restrict__ resid,
                      float* __restrict__ C, int M, int N, int K)
{
    constexpr int WM  = BM/32;     // warps along m (4 or 2)
    constexpr int WN  = 8/WM;      // warps along n (2 or 4)
    constexpr int WTN = 128/WN;    // warp n-tile (64 or 32)
    constexpr int NT  = WTN/8;     // n-subtiles per warp (8 or 4)

    __shared__ unsigned As[BM][36];
    __shared__ unsigned Bs[32][132];

    int tid = threadIdx.x;
    int warp = tid >> 5, lane = tid & 31;
    int g = lane >> 2, t = lane & 3;
    int wm = warp % WM, wn = warp / WM;
    int bm = blockIdx.y * BM, bn = blockIdx.x * 128;

    float acc[2][NT][4];
    #pragma unroll
    for (int mt = 0; mt < 2; mt++)
        #pragma unroll
        for (int nt = 0; nt < NT; nt++)
            #pragma unroll
            for (int i = 0; i < 4; i++) acc[mt][nt][i] = 0.f;

    for (int k0 = 0; k0 < K; k0 += 32) {
        // stage A tile [BM][32], cvt to tf32
        #pragma unroll
        for (int v = 0; v < BM/32; v++) {
            int slot = tid + 256*v;
            int r = slot >> 3, c4 = (slot & 7) * 4;
            float4 av = *(const float4*)&A[(size_t)(bm + r)*K + k0 + c4];
            uint4 u = make_uint4(tf32_of(av.x), tf32_of(av.y), tf32_of(av.z), tf32_of(av.w));
            *(uint4*)&As[r][c4] = u;
        }
        // stage B tile [32][128], cvt to tf32
        #pragma unroll
        for (int v = 0; v < 4; v++) {
            int slot = tid + 256*v;
            int kr = slot >> 5, c4 = (slot & 31) * 4;
            float4 bv = *(const float4*)&Bm[(size_t)(k0 + kr)*N + bn + c4];
            uint4 u = make_uint4(tf32_of(bv.x), tf32_of(bv.y), tf32_of(bv.z), tf32_of(bv.w));
            *(uint4*)&Bs[kr][c4] = u;
        }
        __syncthreads();
        #pragma unroll
        for (int kk = 0; kk < 4; kk++) {
            int kb = kk * 8;
            unsigned af[2][4], bf[NT][2];
            #pragma unroll
            for (int mt = 0; mt < 2; mt++) {
                int m = wm*32 + mt*16;
                af[mt][0] = As[m + g    ][kb + t    ];
                af[mt][1] = As[m + g + 8][kb + t    ];
                af[mt][2] = As[m + g    ][kb + t + 4];
                af[mt][3] = As[m + g + 8][kb + t + 4];
            }
            #pragma unroll
            for (int nt = 0; nt < NT; nt++) {
                int n = wn*WTN + nt*8 + g;
                bf[nt][0] = Bs[kb + t    ][n];
                bf[nt][1] = Bs[kb + t + 4][n];
            }
            #pragma unroll
            for (int mt = 0; mt < 2; mt++)
                #pragma unroll
                for (int nt = 0; nt < NT; nt++)
                    mma_tf32(acc[mt][nt], af[mt], bf[nt]);
        }
        __syncthreads();
    }
    // epilogue: each (mt,nt) owns rows {r0, r0+8}, cols {col, col+1}
    #pragma unroll
    for (int mt = 0; mt < 2; mt++) {
        int r0 = bm + wm*32 + mt*16 + g;
        #pragma unroll
        for (int nt = 0; nt < NT; nt++) {
            int col = bn + wn*WTN + nt*8 + 2*t;
            float2 v0 = make_float2(acc[mt][nt][0], acc[mt][nt][1]);
            float2 v1 = make_float2(acc[mt][nt][2], acc[mt][nt][3]);
            if (HASB) {
                float2 bb = *(const float2*)&bias[col];
                v0.x += bb.x; v0.y += bb.y; v1.x += bb.x; v1.y += bb.y;
            }
            if (GELU) {
                v0.x = 0.5f*v0.x*(1.f + erff(v0.x*0.70710678118f));
                v0.y = 0.5f*v0.y*(1.f + erff(v0.y*0.70710678118f));
                v1.x = 0.5f*v1.x*(1.f + erff(v1.x*0.70710678118f));
                v1.y = 0.5f*v1.y*(1.f + erff(v1.y*0.70710678118f));
            }
            if (HASR) {
                float2 r0v = *(const float2*)&resid[(size_t)r0*N + col];
                float2 r1v = *(const float2*)&resid[(size_t)(r0+8)*N + col];
                v0.x += r0v.x; v0.y += r0v.y; v1.x += r1v.x; v1.y += r1v.y;
            }
            *(float2*)&C[(size_t)r0*N + col]     = v0;
            *(float2*)&C[(size_t)(r0+8)*N + col] = v1;
        }
    }
}

// ---------------- flash attention: block = (b, h, 64 q-rows); j-tiles of 64 ----------------
// inner products use packed f32x2 FMA (exact fp32, 2 MACs/issue)
__global__ __launch_bounds__(256, 2)
void attn_kernel(const float* __restrict__ qkv, const float* __restrict__ pos,
                 float* __restrict__ out)
{
    extern __shared__ float sm[];
    float (*Qs)[68] = (float(*)[68])sm;              // [k][i]
    float (*Ks)[68] = (float(*)[68])(sm + 64*68);    // [k][j]
    float (*Vs)[68] = (float(*)[68])(sm + 2*64*68);  // [j][d]
    float (*Ps)[68] = (float(*)[68])(sm + 3*64*68);  // [j][i]

    int bq = blockIdx.x, h = blockIdx.y, b = blockIdx.z;
    int i0 = bq * 64;
    int tid = threadIdx.x;
    int ty = tid >> 4, tx = tid & 15;      // rows ty*4.., cols tx*4..
    const float* base = qkv + (size_t)b * Ln * QKV3n;

    // load Q tile transposed into Qs[k][i]
    #pragma unroll
    for (int v = 0; v < 4; v++) {
        int f = tid + 256*v;
        int r = f >> 4, kc = (f & 15) * 4;
        float4 qv = *(const float4*)&base[(size_t)(i0 + r)*QKV3n + h*64 + kc];
        Qs[kc+0][r] = qv.x; Qs[kc+1][r] = qv.y; Qs[kc+2][r] = qv.z; Qs[kc+3][r] = qv.w;
    }

    float m[4], l[4];
    unsigned long long o2[4][2];
    #pragma unroll
    for (int i = 0; i < 4; i++) {
        m[i] = -1e30f; l[i] = 0.f;
        o2[i][0] = 0ull; o2[i][1] = 0ull;
    }

    const float* posb = pos + ((size_t)h*Ln + i0)*Ln;

    for (int jt = 0; jt < 16; jt++) {
        int j0 = jt * 64;
        __syncthreads();   // prev PV done (and Q tile ready on first iter)
        // load K tile transposed, V tile direct
        #pragma unroll
        for (int v = 0; v < 4; v++) {
            int f = tid + 256*v;
            int r = f >> 4, kc = (f & 15) * 4;
            float4 kv = *(const float4*)&base[(size_t)(j0 + r)*QKV3n + INNERn + h*64 + kc];
            Ks[kc+0][r] = kv.x; Ks[kc+1][r] = kv.y; Ks[kc+2][r] = kv.z; Ks[kc+3][r] = kv.w;
            float4 vv = *(const float4*)&base[(size_t)(j0 + r)*QKV3n + 2*INNERn + h*64 + kc];
            *(float4*)&Vs[r][kc] = vv;
        }
        // prefetch pos bias for this tile
        float4 pv[4];
        #pragma unroll
        for (int i = 0; i < 4; i++)
            pv[i] = *(const float4*)&posb[(size_t)(ty*4 + i)*Ln + j0 + tx*4];
        __syncthreads();

        // S = Q @ K^T  (64x64x64) packed f32x2
        unsigned long long s2[4][2];
        #pragma unroll
        for (int i = 0; i < 4; i++) { s2[i][0] = 0ull; s2[i][1] = 0ull; }
        #pragma unroll 8
        for (int k = 0; k < 64; k++) {
            float4 a4 = *(const float4*)&Qs[k][ty*4];
            float4 b4 = *(const float4*)&Ks[k][tx*4];
            unsigned long long bp0 = pk(b4.x, b4.y), bp1 = pk(b4.z, b4.w);
            unsigned long long ad;
            ad = pk(a4.x, a4.x); fma2(s2[0][0], ad, bp0); fma2(s2[0][1], ad, bp1);
            ad = pk(a4.y, a4.y); fma2(s2[1][0], ad, bp0); fma2(s2[1][1], ad, bp1);
            ad = pk(a4.z, a4.z); fma2(s2[2][0], ad, bp0); fma2(s2[2][1], ad, bp1);
            ad = pk(a4.w, a4.w); fma2(s2[3][0], ad, bp0); fma2(s2[3][1], ad, bp1);
        }
        // unpack, scale + pos bias
        float s[4][4];
        #pragma unroll
        for (int i = 0; i < 4; i++) {
            float2 p0 = upk(s2[i][0]), p1 = upk(s2[i][1]);
            s[i][0] = p0.x*0.125f + pv[i].x;
            s[i][1] = p0.y*0.125f + pv[i].y;
            s[i][2] = p1.x*0.125f + pv[i].z;
            s[i][3] = p1.y*0.125f + pv[i].w;
        }
        // online softmax stats per row (reduce across tx = low 4 lane bits)
        #pragma unroll
        for (int i = 0; i < 4; i++) {
            float tm = fmaxf(fmaxf(s[i][0], s[i][1]), fmaxf(s[i][2], s[i][3]));
            #pragma unroll
            for (int off = 1; off < 16; off <<= 1)
                tm = fmaxf(tm, __shfl_xor_sync(0xffffffffu, tm, off));
            float mn = fmaxf(m[i], tm);
            float corr = expf(m[i] - mn);
            float e0 = expf(s[i][0] - mn), e1 = expf(s[i][1] - mn);
            float e2 = expf(s[i][2] - mn), e3 = expf(s[i][3] - mn);
            s[i][0] = e0; s[i][1] = e1; s[i][2] = e2; s[i][3] = e3;
            float ts = e0 + e1 + e2 + e3;
            #pragma unroll
            for (int off = 1; off < 16; off <<= 1)
                ts += __shfl_xor_sync(0xffffffffu, ts, off);
            l[i] = l[i]*corr + ts;
            m[i] = mn;
            unsigned long long cc = pk(corr, corr);
            o2[i][0] = mul2(o2[i][0], cc);
            o2[i][1] = mul2(o2[i][1], cc);
        }
        // write P transposed: Ps[j][i]
        #pragma unroll
        for (int j = 0; j < 4; j++)
            #pragma unroll
            for (int i = 0; i < 4; i++)
                Ps[tx*4 + j][ty*4 + i] = s[i][j];
        __syncthreads();
        // O += P @ V  (64x64x64) packed f32x2
        #pragma unroll 8
        for (int jj = 0; jj < 64; jj++) {
            float4 a4 = *(const float4*)&Ps[jj][ty*4];
            float4 b4 = *(const float4*)&Vs[jj][tx*4];
            unsigned long long bp0 = pk(b4.x, b4.y), bp1 = pk(b4.z, b4.w);
            unsigned long long ad;
            ad = pk(a4.x, a4.x); fma2(o2[0][0], ad, bp0); fma2(o2[0][1], ad, bp1);
            ad = pk(a4.y, a4.y); fma2(o2[1][0], ad, bp0); fma2(o2[1][1], ad, bp1);
            ad = pk(a4.z, a4.z); fma2(o2[2][0], ad, bp0); fma2(o2[2][1], ad, bp1);
            ad = pk(a4.w, a4.w); fma2(o2[3][0], ad, bp0); fma2(o2[3][1], ad, bp1);
        }
    }
    // normalize + write
    #pragma unroll
    for (int i = 0; i < 4; i++) {
        float inv = 1.f / l[i];
        float2 q0 = upk(o2[i][0]), q1 = upk(o2[i][1]);
        float* op = &out[((size_t)b*Ln + i0 + ty*4 + i)*INNERn + h*64 + tx*4];
        float2 w0 = make_float2(q0.x*inv, q0.y*inv);
        float2 w1 = make_float2(q1.x*inv, q1.y*inv);
        *(float2*)&op[0] = w0;
        *(float2*)&op[2] = w1;
    }
}

// ---------------- SE pool tail ----------------
__global__ void se1_kernel(const float* __restrict__ wv, const float* __restrict__ w1,
                           const float* __restrict__ b1, float* __restrict__ t)
{
    int tid = threadIdx.x;                            // 512
    int b = tid >> 7, j = tid & 127;
    float acc = b1[j];
    for (int l = 0; l < Ln; l++) acc += wv[b*Ln + l] * w1[l*128 + j];
    t[tid] = fmaxf(acc, 0.f);
}

__global__ void se2_kernel(const float* __restrict__ t, const float* __restrict__ w2,
                           const float* __restrict__ b2, float* __restrict__ u)
{
    int idx = blockIdx.x * 256 + threadIdx.x;         // 4096
    int b = idx >> 10, l = idx & (Ln-1);
    float acc = b2[l];
    #pragma unroll
    for (int j = 0; j < 128; j++) acc += t[b*128 + j] * w2[j*Ln + l];
    u[idx] = 1.f / (1.f + expf(-acc));
}

__global__ void pool_out_kernel(const float* __restrict__ u, const float* __restrict__ x,
                                float* __restrict__ out)
{
    int b = blockIdx.x, d = threadIdx.x;              // 4 x 256
    float acc = 0.f;
    for (int l = 0; l < Ln; l++) acc += u[b*Ln + l] * x[((size_t)b*Ln + l)*DIMn + d];
    out[b*DIMn + d] = acc;
}

// ---------------- host launch ----------------
extern "C" void kernel_launch(void* const* d_in, const int* in_sizes, int n_in,
                              void* d_out, int out_size)
{
    const float* img     = (const float*)d_in[0];
    const float* conv1_w = (const float*)d_in[1];
    const float* conv1_b = (const float*)d_in[2];
    const float* conv2_w = (const float*)d_in[3];
    const float* conv2_b = (const float*)d_in[4];
    const float* conv3_w = (const float*)d_in[5];
    const float* conv3_b = (const float*)d_in[6];
    const float* ln1_s   = (const float*)d_in[7];
    const float* ln1_b   = (const float*)d_in[8];
    const float* qkv_w   = (const float*)d_in[9];
    const float* pos     = (const float*)d_in[10];
    const float* out_w   = (const float*)d_in[11];
    const float* out_b   = (const float*)d_in[12];
    const float* ln2_s   = (const float*)d_in[13];
    const float* ln2_b   = (const float*)d_in[14];
    const float* ff_w1   = (const float*)d_in[15];
    const float* ff_b1   = (const float*)d_in[16];
    const float* ff_w2   = (const float*)d_in[17];
    const float* ff_b2   = (const float*)d_in[18];
    const float* se_w1   = (const float*)d_in[19];
    const float* se_b1   = (const float*)d_in[20];
    const float* se_w2   = (const float*)d_in[21];
    const float* se_b2   = (const float*)d_in[22];
    float* out = (float*)d_out;

    float *c1, *c2, *x, *h, *qkv, *att, *mlp, *pw, *t, *u;
    cudaGetSymbolAddress((void**)&c1,  g_c1);
    cudaGetSymbolAddress((void**)&c2,  g_c2);
    cudaGetSymbolAddress((void**)&x,   g_x);
    cudaGetSymbolAddress((void**)&h,   g_h);
    cudaGetSymbolAddress((void**)&qkv, g_qkv);
    cudaGetSymbolAddress((void**)&att, g_att);
    cudaGetSymbolAddress((void**)&mlp, g_mlp);
    cudaGetSymbolAddress((void**)&pw,  g_pw);
    cudaGetSymbolAddress((void**)&t,   g_t);
    cudaGetSymbolAddress((void**)&u,   g_u);

    const int ATTN_SMEM = 4 * 64 * 68 * 4;  // 69632 bytes
    cudaFuncSetAttribute(attn_kernel, cudaFuncAttributeMaxDynamicSharedMemorySize, ATTN_SMEM);

    // conv patch embed
    conv1_kernel<<<(Bn*256*2*Ln + 255)/256, 256>>>(img, conv1_w, conv1_b, c1);
    conv2_kernel<<<dim3(Ln/16, Bn), 256>>>(c1, conv2_w, conv2_b, c2);
    conv3_kernel<<<dim3(Ln/16, Bn), 256>>>(c2, conv3_w, conv3_b, x);

    for (int lyr = 0; lyr < DEPTHn; lyr++) {
        // attention block
        ln_kernel<<<ROWS, 256>>>(x, ln1_s + lyr*DIMn, ln1_b + lyr*DIMn, h);
        gemm_tf32_kernel<128,false,false,false><<<dim3(QKV3n/128, ROWS/128), 256>>>(
            h, qkv_w + (size_t)lyr*DIMn*QKV3n, nullptr, nullptr, qkv, ROWS, QKV3n, DIMn);
        attn_kernel<<<dim3(Ln/64, HEADSn, Bn), 256, ATTN_SMEM>>>(
            qkv, pos + (size_t)lyr*HEADSn*Ln*Ln, att);
        gemm_tf32_kernel<64,false,true,true><<<dim3(DIMn/128, ROWS/64), 256>>>(
            att, out_w + (size_t)lyr*INNERn*DIMn, out_b + lyr*DIMn, x, x, ROWS, DIMn, INNERn);
        // MLP block
        ln_kernel<<<ROWS, 256>>>(x, ln2_s + lyr*DIMn, ln2_b + lyr*DIMn, h);
        gemm_tf32_kernel<128,true,true,false><<<dim3(MLPn/128, ROWS/128), 256>>>(
            h, ff_w1 + (size_t)lyr*DIMn*MLPn, ff_b1 + lyr*MLPn, nullptr, mlp, ROWS, MLPn, DIMn);
        gemm_tf32_kernel<64,false,true,true><<<dim3(DIMn/128, ROWS/64), 256>>>(
            mlp, ff_w2 + (size_t)lyr*MLPn*DIMn, ff_b2 + lyr*DIMn, x, x, ROWS, DIMn, MLPn);
    }

    // SE attention pool
    meanpool_kernel<<<ROWS, 256>>>(x, pw);
    se1_kernel<<<1, 512>>>(pw, se_w1, se_b1, t);
    se2_kernel<<<(Bn*Ln)/256, 256>>>(t, se_w2, se_b2, u);
    pool_out_kernel<<<Bn, 256>>>(u, x, out);
}

// round 4
// speedup vs baseline: 4.0082x; 1.0738x over previous
#include <cuda_runtime.h>
#include <cuda_bf16.h>
#include <math.h>

// ---------------- problem constants ----------------
#define Bn    4
#define Ln    1024
#define DIMn  256
#define HEADSn 8
#define DHn   64
#define DEPTHn 2
#define MLPn  512
#define INNERn 512
#define QKV3n 1536
#define ROWS  (Bn*Ln)     // 4096

// ---------------- scratch (device globals; no allocs allowed) ----------------
__device__ float g_c1[Bn*256*2*Ln];     // 8MB
__device__ float g_c2[Bn*256*Ln];       // 4MB
__device__ float g_x [ROWS*DIMn];       // 4MB
__device__ float g_h [ROWS*DIMn];       // 4MB
__device__ float g_qkv[ROWS*QKV3n];     // 25MB
__device__ float g_att[ROWS*INNERn];    // 8MB
__device__ float g_mlp[ROWS*MLPn];      // 8MB
__device__ float g_pw[ROWS];
__device__ float g_t [Bn*128];
__device__ float g_u [Bn*Ln];

// ---------------- helpers: tf32 mma ----------------
__device__ __forceinline__ unsigned tf32_of(float f) {
    unsigned u; asm("cvt.rna.tf32.f32 %0, %1;" : "=r"(u) : "f"(f)); return u;
}
__device__ __forceinline__ void mma_tf32(float* c, const unsigned* a, const unsigned* b) {
    asm volatile("mma.sync.aligned.m16n8k8.row.col.f32.tf32.tf32.f32 "
        "{%0,%1,%2,%3}, {%4,%5,%6,%7}, {%8,%9}, {%0,%1,%2,%3};"
        : "+f"(c[0]), "+f"(c[1]), "+f"(c[2]), "+f"(c[3])
        : "r"(a[0]), "r"(a[1]), "r"(a[2]), "r"(a[3]), "r"(b[0]), "r"(b[1]));
}

// ---------------- conv1: 1->256, kernel (1,3), pad (0,1) ----------------
__global__ void conv1_kernel(const float* __restrict__ img, const float* __restrict__ w,
                             const float* __restrict__ bias, float* __restrict__ out)
{
    int idx = blockIdx.x * 256 + threadIdx.x;        // [b][c][h][l]
    if (idx >= Bn*256*2*Ln) return;
    int l  = idx & (Ln-1);
    int hh = (idx >> 10) & 1;
    int c  = (idx >> 11) & 255;
    int b  = idx >> 19;
    const float* ir = img + ((size_t)b*2 + hh)*Ln;
    float acc = bias[c];
    #pragma unroll
    for (int k = 0; k < 3; k++) {
        int ll = l + k - 1;
        if (ll >= 0 && ll < Ln) acc += ir[ll] * w[c*3 + k];
    }
    out[idx] = fmaxf(acc, 0.f);
}

// ---------------- conv2: 256->256, kernel (2,3), pad (0,1), H 2->1 ----------------
__global__ void conv2_kernel(const float* __restrict__ c1, const float* __restrict__ w,
                             const float* __restrict__ bias, float* __restrict__ out)
{
    int b  = blockIdx.y;
    int l0 = blockIdx.x * 16;
    int tid = threadIdx.x;                            // 256 = c_out
    __shared__ float patch[512][18];                  // (ci*2+h) x pos, 36KB
    for (int idx = tid; idx < 512*18; idx += 256) {
        int ch = idx / 18, p = idx % 18;
        int ci = ch >> 1, hh = ch & 1;
        int l = l0 - 1 + p;
        float v = 0.f;
        if (l >= 0 && l < Ln) v = c1[(((size_t)b*256 + ci)*2 + hh)*Ln + l];
        patch[ch][p] = v;
    }
    __syncthreads();
    float acc[16];
    float bb = bias[tid];
    #pragma unroll
    for (int t = 0; t < 16; t++) acc[t] = bb;
    const float* wr = w + (size_t)tid * 1536;         // [ci][h][k]
    for (int ci = 0; ci < 256; ci++) {
        #pragma unroll
        for (int hh = 0; hh < 2; hh++) {
            const float* wk = wr + (ci*2 + hh)*3;
            float w0 = wk[0], w1 = wk[1], w2 = wk[2];
            const float* pr = patch[ci*2 + hh];
            #pragma unroll
            for (int t = 0; t < 16; t++)
                acc[t] += w0*pr[t] + w1*pr[t+1] + w2*pr[t+2];
        }
    }
    #pragma unroll
    for (int t = 0; t < 16; t++)
        out[((size_t)b*256 + tid)*Ln + l0 + t] = fmaxf(acc[t], 0.f);
}

// ---------------- conv3: 256->DIM, kernel (1,3), pad (0,1); writes x[b,l,d] ----------------
__global__ void conv3_kernel(const float* __restrict__ c2, const float* __restrict__ w,
                             const float* __restrict__ bias, float* __restrict__ xout)
{
    int b  = blockIdx.y;
    int l0 = blockIdx.x * 16;
    int tid = threadIdx.x;                            // 256 = d
    __shared__ float patch[256][18];                  // 18KB
    for (int idx = tid; idx < 256*18; idx += 256) {
        int ci = idx / 18, p = idx % 18;
        int l = l0 - 1 + p;
        patch[ci][p] = (l >= 0 && l < Ln) ? c2[((size_t)b*256 + ci)*Ln + l] : 0.f;
    }
    __syncthreads();
    float acc[16];
    float bb = bias[tid];
    #pragma unroll
    for (int t = 0; t < 16; t++) acc[t] = bb;
    const float* wr = w + (size_t)tid * 768;
    for (int ci = 0; ci < 256; ci++) {
        float w0 = wr[ci*3+0], w1 = wr[ci*3+1], w2 = wr[ci*3+2];
        const float* pr = patch[ci];
        #pragma unroll
        for (int t = 0; t < 16; t++)
            acc[t] += w0*pr[t] + w1*pr[t+1] + w2*pr[t+2];
    }
    #pragma unroll
    for (int t = 0; t < 16; t++)
        xout[((size_t)b*Ln + l0 + t)*DIMn + tid] = fmaxf(acc[t], 0.f);
}

// ---------------- layernorm / mean pool (block per row, 256 threads) ----------------
__global__ void ln_kernel(const float* __restrict__ x, const float* __restrict__ s,
                          const float* __restrict__ b, float* __restrict__ out)
{
    int row = blockIdx.x, tid = threadIdx.x;
    __shared__ float red[256];
    float v = x[(size_t)row*DIMn + tid];
    red[tid] = v; __syncthreads();
    for (int st = 128; st > 0; st >>= 1) { if (tid < st) red[tid] += red[tid+st]; __syncthreads(); }
    float m = red[0] * (1.f/DIMn); __syncthreads();
    float d = v - m;
    red[tid] = d*d; __syncthreads();
    for (int st = 128; st > 0; st >>= 1) { if (tid < st) red[tid] += red[tid+st]; __syncthreads(); }
    float var = red[0] * (1.f/DIMn);
    out[(size_t)row*DIMn + tid] = d * rsqrtf(var + 1e-5f) * s[tid] + b[tid];
}

__global__ void meanpool_kernel(const float* __restrict__ x, float* __restrict__ w)
{
    int row = blockIdx.x, tid = threadIdx.x;
    __shared__ float red[256];
    red[tid] = x[(size_t)row*DIMn + tid]; __syncthreads();
    for (int st = 128; st > 0; st >>= 1) { if (tid < st) red[tid] += red[tid+st]; __syncthreads(); }
    if (tid == 0) w[row] = red[0] * (1.f/DIMn);
}

// ---------------- 3xtf32 tensor-core GEMM: near-fp32 accuracy ----------------
// C = A[MxK] @ B[KxN] (+bias)(+gelu)(+resid). BN=128, 256 threads = 8 warps.
// A,B split into tf32 hi+lo; acc += hi*lo + lo*hi + hi*hi.
template<int BM, bool GELU, bool HASB, bool HASR>
__global__ __launch_bounds__(256)
void gemm_tf32_kernel(const float* __restrict__ A, const float* __restrict__ Bm,
                      const float* __restrict__ bias, const float* __restrict__ resid,
                      float* __restrict__ C, int M, int N, int K)
{
    constexpr int WM  = BM/32;     // warps along m (4 or 2)
    constexpr int WN  = 8/WM;      // warps along n (2 or 4)
    constexpr int WTN = 128/WN;    // warp n-tile (64 or 32)
    constexpr int NT  = WTN/8;     // n-subtiles per warp (8 or 4)

    extern __shared__ unsigned smu[];
    unsigned* As_hi = smu;                       // [BM][36]
    unsigned* As_lo = smu + BM*36;
    unsigned* Bs_hi = smu + 2*BM*36;             // [32][132]
    unsigned* Bs_lo = smu + 2*BM*36 + 32*132;

    int tid = threadIdx.x;
    int warp = tid >> 5, lane = tid & 31;
    int g = lane >> 2, t = lane & 3;
    int wm = warp % WM, wn = warp / WM;
    int bm = blockIdx.y * BM, bn = blockIdx.x * 128;

    float acc[2][NT][4];
    #pragma unroll
    for (int mt = 0; mt < 2; mt++)
        #pragma unroll
        for (int nt = 0; nt < NT; nt++)
            #pragma unroll
            for (int i = 0; i < 4; i++) acc[mt][nt][i] = 0.f;

    for (int k0 = 0; k0 < K; k0 += 32) {
        // stage A tile [BM][32] as hi/lo tf32
        #pragma unroll
        for (int v = 0; v < BM/32; v++) {
            int slot = tid + 256*v;
            int r = slot >> 3, c4 = (slot & 7) * 4;
            float4 av = *(const float4*)&A[(size_t)(bm + r)*K + k0 + c4];
            unsigned h0 = tf32_of(av.x), h1 = tf32_of(av.y), h2 = tf32_of(av.z), h3 = tf32_of(av.w);
            *(uint4*)&As_hi[r*36 + c4] = make_uint4(h0, h1, h2, h3);
            *(uint4*)&As_lo[r*36 + c4] = make_uint4(
                tf32_of(av.x - __uint_as_float(h0)), tf32_of(av.y - __uint_as_float(h1)),
                tf32_of(av.z - __uint_as_float(h2)), tf32_of(av.w - __uint_as_float(h3)));
        }
        // stage B tile [32][128] as hi/lo tf32
        #pragma unroll
        for (int v = 0; v < 4; v++) {
            int slot = tid + 256*v;
            int kr = slot >> 5, c4 = (slot & 31) * 4;
            float4 bv = *(const float4*)&Bm[(size_t)(k0 + kr)*N + bn + c4];
            unsigned h0 = tf32_of(bv.x), h1 = tf32_of(bv.y), h2 = tf32_of(bv.z), h3 = tf32_of(bv.w);
            *(uint4*)&Bs_hi[kr*132 + c4] = make_uint4(h0, h1, h2, h3);
            *(uint4*)&Bs_lo[kr*132 + c4] = make_uint4(
                tf32_of(bv.x - __uint_as_float(h0)), tf32_of(bv.y - __uint_as_float(h1)),
                tf32_of(bv.z - __uint_as_float(h2)), tf32_of(bv.w - __uint_as_float(h3)));
        }
        __syncthreads();
        #pragma unroll
        for (int kk = 0; kk < 4; kk++) {
            int kb = kk * 8;
            unsigned ah[2][4], al[2][4];
            #pragma unroll
            for (int mt = 0; mt < 2; mt++) {
                int m = wm*32 + mt*16;
                ah[mt][0] = As_hi[(m + g    )*36 + kb + t    ];
                ah[mt][1] = As_hi[(m + g + 8)*36 + kb + t    ];
                ah[mt][2] = As_hi[(m + g    )*36 + kb + t + 4];
                ah[mt][3] = As_hi[(m + g + 8)*36 + kb + t + 4];
                al[mt][0] = As_lo[(m + g    )*36 + kb + t    ];
                al[mt][1] = As_lo[(m + g + 8)*36 + kb + t    ];
                al[mt][2] = As_lo[(m + g    )*36 + kb + t + 4];
                al[mt][3] = As_lo[(m + g + 8)*36 + kb + t + 4];
            }
            #pragma unroll
            for (int nt = 0; nt < NT; nt++) {
                int n = wn*WTN + nt*8 + g;
                unsigned bh[2], bl[2];
                bh[0] = Bs_hi[(kb + t    )*132 + n];
                bh[1] = Bs_hi[(kb + t + 4)*132 + n];
                bl[0] = Bs_lo[(kb + t    )*132 + n];
                bl[1] = Bs_lo[(kb + t + 4)*132 + n];
                #pragma unroll
                for (int mt = 0; mt < 2; mt++) {
                    mma_tf32(acc[mt][nt], ah[mt], bl);   // hi*lo
                    mma_tf32(acc[mt][nt], al[mt], bh);   // lo*hi
                    mma_tf32(acc[mt][nt], ah[mt], bh);   // hi*hi
                }
            }
        }
        __syncthreads();
    }
    // epilogue: each (mt,nt) owns rows {r0, r0+8}, cols {col, col+1}
    #pragma unroll
    for (int mt = 0; mt < 2; mt++) {
        int r0 = bm + wm*32 + mt*16 + g;
        #pragma unroll
        for (int nt = 0; nt < NT; nt++) {
            int col = bn + wn*WTN + nt*8 + 2*t;
            float2 v0 = make_float2(acc[mt][nt][0], acc[mt][nt][1]);
            float2 v1 = make_float2(acc[mt][nt][2], acc[mt][nt][3]);
            if (HASB) {
                float2 bb = *(const float2*)&bias[col];
                v0.x += bb.x; v0.y += bb.y; v1.x += bb.x; v1.y += bb.y;
            }
            if (GELU) {
                v0.x = 0.5f*v0.x*(1.f + erff(v0.x*0.70710678118f));
                v0.y = 0.5f*v0.y*(1.f + erff(v0.y*0.70710678118f));
                v1.x = 0.5f*v1.x*(1.f + erff(v1.x*0.70710678118f));
                v1.y = 0.5f*v1.y*(1.f + erff(v1.y*0.70710678118f));
            }
            if (HASR) {
                float2 r0v = *(const float2*)&resid[(size_t)r0*N + col];
                float2 r1v = *(const float2*)&resid[(size_t)(r0+8)*N + col];
                v0.x += r0v.x; v0.y += r0v.y; v1.x += r1v.x; v1.y += r1v.y;
            }
            *(float2*)&C[(size_t)r0*N + col]     = v0;
            *(float2*)&C[(size_t)(r0+8)*N + col] = v1;
        }
    }
}

// ---------------- flash attention with tf32 mma ----------------
// Block = (b, h, 64 q-rows), 128 threads = 4 warps, each warp a 16-row band.
// smem tiles (tf32): Qs[m][d], Ks[d][j], Vs[j][d], Ps[m][j]; all stride 68.
__global__ __launch_bounds__(128, 3)
void attn_kernel(const float* __restrict__ qkv, const float* __restrict__ pos,
                 float* __restrict__ out)
{
    extern __shared__ unsigned smu[];
    unsigned* Qs = smu;                // [64][68]
    unsigned* Ks = smu + 64*68;        // [64][68]  (d-major: Ks[d][j])
    unsigned* Vs = smu + 2*64*68;      // [64][68]  (j-major: Vs[j][d])
    unsigned* Ps = smu + 3*64*68;      // [64][68]

    int bq = blockIdx.x, h = blockIdx.y, b = blockIdx.z;
    int i0 = bq * 64;
    int tid = threadIdx.x;
    int warp = tid >> 5, lane = tid & 31;
    int g = lane >> 2, t = lane & 3;
    int m0 = warp * 16;
    const float* base = qkv + (size_t)b * Ln * QKV3n;

    // load Q tile [64][64] -> tf32
    #pragma unroll
    for (int v = 0; v < 8; v++) {
        int f = tid + 128*v;
        int r = f >> 4, c4 = (f & 15) * 4;
        float4 qv = *(const float4*)&base[(size_t)(i0 + r)*QKV3n + h*64 + c4];
        *(uint4*)&Qs[r*68 + c4] = make_uint4(tf32_of(qv.x), tf32_of(qv.y), tf32_of(qv.z), tf32_of(qv.w));
    }

    float o[8][4];
    #pragma unroll
    for (int nt = 0; nt < 8; nt++)
        #pragma unroll
        for (int i = 0; i < 4; i++) o[nt][i] = 0.f;
    float mrow0 = -1e30f, mrow1 = -1e30f, lrow0 = 0.f, lrow1 = 0.f;

    // pos row pointers for this thread's two rows
    const float* pr0 = pos + ((size_t)(h*Ln + i0 + m0 + g    ))*Ln;
    const float* pr1 = pos + ((size_t)(h*Ln + i0 + m0 + g + 8))*Ln;

    for (int jt = 0; jt < 16; jt++) {
        int j0 = jt * 64;
        __syncthreads();   // prev PV reads of Vs done; Q ready on first iter
        // load K (transposed -> Ks[d][j]) and V (direct -> Vs[j][d]) as tf32
        #pragma unroll
        for (int v = 0; v < 8; v++) {
            int f = tid + 128*v;
            int r = f >> 4, c4 = (f & 15) * 4;    // r = j, c4 = d
            float4 kv = *(const float4*)&base[(size_t)(j0 + r)*QKV3n + INNERn + h*64 + c4];
            Ks[(c4+0)*68 + r] = tf32_of(kv.x);
            Ks[(c4+1)*68 + r] = tf32_of(kv.y);
            Ks[(c4+2)*68 + r] = tf32_of(kv.z);
            Ks[(c4+3)*68 + r] = tf32_of(kv.w);
            float4 vv = *(const float4*)&base[(size_t)(j0 + r)*QKV3n + 2*INNERn + h*64 + c4];
            *(uint4*)&Vs[r*68 + c4] = make_uint4(tf32_of(vv.x), tf32_of(vv.y), tf32_of(vv.z), tf32_of(vv.w));
        }
        __syncthreads();

        // S = Q @ K^T : warp band m0..m0+15, cols 0..63
        float sa[8][4];
        #pragma unroll
        for (int nt = 0; nt < 8; nt++)
            #pragma unroll
            for (int i = 0; i < 4; i++) sa[nt][i] = 0.f;
        #pragma unroll
        for (int kc = 0; kc < 8; kc++) {
            int kb = kc * 8;
            unsigned a[4];
            a[0] = Qs[(m0 + g    )*68 + kb + t    ];
            a[1] = Qs[(m0 + g + 8)*68 + kb + t    ];
            a[2] = Qs[(m0 + g    )*68 + kb + t + 4];
            a[3] = Qs[(m0 + g + 8)*68 + kb + t + 4];
            #pragma unroll
            for (int nt = 0; nt < 8; nt++) {
                unsigned bb[2];
                bb[0] = Ks[(kb + t    )*68 + nt*8 + g];
                bb[1] = Ks[(kb + t + 4)*68 + nt*8 + g];
                mma_tf32(sa[nt], a, bb);
            }
        }
        // scale + pos bias
        #pragma unroll
        for (int nt = 0; nt < 8; nt++) {
            float2 p0 = *(const float2*)&pr0[j0 + nt*8 + 2*t];
            float2 p1 = *(const float2*)&pr1[j0 + nt*8 + 2*t];
            sa[nt][0] = sa[nt][0]*0.125f + p0.x;
            sa[nt][1] = sa[nt][1]*0.125f + p0.y;
            sa[nt][2] = sa[nt][2]*0.125f + p1.x;
            sa[nt][3] = sa[nt][3]*0.125f + p1.y;
        }
        // row max across this j-tile (reduce over t lanes: xor 1,2)
        float mx0 = -1e30f, mx1 = -1e30f;
        #pragma unroll
        for (int nt = 0; nt < 8; nt++) {
            mx0 = fmaxf(mx0, fmaxf(sa[nt][0], sa[nt][1]));
            mx1 = fmaxf(mx1, fmaxf(sa[nt][2], sa[nt][3]));
        }
        mx0 = fmaxf(mx0, __shfl_xor_sync(0xffffffffu, mx0, 1));
        mx0 = fmaxf(mx0, __shfl_xor_sync(0xffffffffu, mx0, 2));
        mx1 = fmaxf(mx1, __shfl_xor_sync(0xffffffffu, mx1, 1));
        mx1 = fmaxf(mx1, __shfl_xor_sync(0xffffffffu, mx1, 2));
        float mn0 = fmaxf(mrow0, mx0), mn1 = fmaxf(mrow1, mx1);
        float corr0 = expf(mrow0 - mn0), corr1 = expf(mrow1 - mn1);
        // exp + row sum + write P (tf32)
        float ts0 = 0.f, ts1 = 0.f;
        #pragma unroll
        for (int nt = 0; nt < 8; nt++) {
            float e0 = expf(sa[nt][0] - mn0);
            float e1 = expf(sa[nt][1] - mn0);
            float e2 = expf(sa[nt][2] - mn1);
            float e3 = expf(sa[nt][3] - mn1);
            ts0 += e0 + e1; ts1 += e2 + e3;
            int c = nt*8 + 2*t;
            Ps[(m0 + g    )*68 + c    ] = tf32_of(e0);
            Ps[(m0 + g    )*68 + c + 1] = tf32_of(e1);
            Ps[(m0 + g + 8)*68 + c    ] = tf32_of(e2);
            Ps[(m0 + g + 8)*68 + c + 1] = tf32_of(e3);
        }
        ts0 += __shfl_xor_sync(0xffffffffu, ts0, 1);
        ts0 += __shfl_xor_sync(0xffffffffu, ts0, 2);
        ts1 += __shfl_xor_sync(0xffffffffu, ts1, 1);
        ts1 += __shfl_xor_sync(0xffffffffu, ts1, 2);
        lrow0 = lrow0*corr0 + ts0;
        lrow1 = lrow1*corr1 + ts1;
        mrow0 = mn0; mrow1 = mn1;
        #pragma unroll
        for (int nt = 0; nt < 8; nt++) {
            o[nt][0] *= corr0; o[nt][1] *= corr0;
            o[nt][2] *= corr1; o[nt][3] *= corr1;
        }
        __syncwarp();
        // O += P @ V : k = j (64), n = d (64)
        #pragma unroll
        for (int kc = 0; kc < 8; kc++) {
            int kb = kc * 8;
            unsigned a[4];
            a[0] = Ps[(m0 + g    )*68 + kb + t    ];
            a[1] = Ps[(m0 + g + 8)*68 + kb + t    ];
            a[2] = Ps[(m0 + g    )*68 + kb + t + 4];
            a[3] = Ps[(m0 + g + 8)*68 + kb + t + 4];
            #pragma unroll
            for (int nt = 0; nt < 8; nt++) {
                unsigned bb[2];
                bb[0] = Vs[(kb + t    )*68 + nt*8 + g];
                bb[1] = Vs[(kb + t + 4)*68 + nt*8 + g];
                mma_tf32(o[nt], a, bb);
            }
        }
    }
    // normalize + write: rows i0+m0+g, i0+m0+g+8; cols h*64 + nt*8 + 2t (+1)
    float inv0 = 1.f / lrow0, inv1 = 1.f / lrow1;
    size_t r0 = (size_t)b*Ln + i0 + m0 + g;
    size_t r1 = r0 + 8;
    #pragma unroll
    for (int nt = 0; nt < 8; nt++) {
        int col = h*64 + nt*8 + 2*t;
        *(float2*)&out[r0*INNERn + col] = make_float2(o[nt][0]*inv0, o[nt][1]*inv0);
        *(float2*)&out[r1*INNERn + col] = make_float2(o[nt][2]*inv1, o[nt][3]*inv1);
    }
}

// ---------------- SE pool tail ----------------
__global__ void se1_kernel(const float* __restrict__ wv, const float* __restrict__ w1,
                           const float* __restrict__ b1, float* __restrict__ t)
{
    int tid = threadIdx.x;                            // 512
    int b = tid >> 7, j = tid & 127;
    float acc = b1[j];
    for (int l = 0; l < Ln; l++) acc += wv[b*Ln + l] * w1[l*128 + j];
    t[tid] = fmaxf(acc, 0.f);
}

__global__ void se2_kernel(const float* __restrict__ t, const float* __restrict__ w2,
                           const float* __restrict__ b2, float* __restrict__ u)
{
    int idx = blockIdx.x * 256 + threadIdx.x;         // 4096
    int b = idx >> 10, l = idx & (Ln-1);
    float acc = b2[l];
    #pragma unroll
    for (int j = 0; j < 128; j++) acc += t[b*128 + j] * w2[j*Ln + l];
    u[idx] = 1.f / (1.f + expf(-acc));
}

__global__ void pool_out_kernel(const float* __restrict__ u, const float* __restrict__ x,
                                float* __restrict__ out)
{
    int b = blockIdx.x, d = threadIdx.x;              // 4 x 256
    float acc = 0.f;
    for (int l = 0; l < Ln; l++) acc += u[b*Ln + l] * x[((size_t)b*Ln + l)*DIMn + d];
    out[b*DIMn + d] = acc;
}

// ---------------- host launch ----------------
extern "C" void kernel_launch(void* const* d_in, const int* in_sizes, int n_in,
                              void* d_out, int out_size)
{
    const float* img     = (const float*)d_in[0];
    const float* conv1_w = (const float*)d_in[1];
    const float* conv1_b = (const float*)d_in[2];
    const float* conv2_w = (const float*)d_in[3];
    const float* conv2_b = (const float*)d_in[4];
    const float* conv3_w = (const float*)d_in[5];
    const float* conv3_b = (const float*)d_in[6];
    const float* ln1_s   = (const float*)d_in[7];
    const float* ln1_b   = (const float*)d_in[8];
    const float* qkv_w   = (const float*)d_in[9];
    const float* pos     = (const float*)d_in[10];
    const float* out_w   = (const float*)d_in[11];
    const float* out_b   = (const float*)d_in[12];
    const float* ln2_s   = (const float*)d_in[13];
    const float* ln2_b   = (const float*)d_in[14];
    const float* ff_w1   = (const float*)d_in[15];
    const float* ff_b1   = (const float*)d_in[16];
    const float* ff_w2   = (const float*)d_in[17];
    const float* ff_b2   = (const float*)d_in[18];
    const float* se_w1   = (const float*)d_in[19];
    const float* se_b1   = (const float*)d_in[20];
    const float* se_w2   = (const float*)d_in[21];
    const float* se_b2   = (const float*)d_in[22];
    float* out = (float*)d_out;

    float *c1, *c2, *x, *h, *qkv, *att, *mlp, *pw, *t, *u;
    cudaGetSymbolAddress((void**)&c1,  g_c1);
    cudaGetSymbolAddress((void**)&c2,  g_c2);
    cudaGetSymbolAddress((void**)&x,   g_x);
    cudaGetSymbolAddress((void**)&h,   g_h);
    cudaGetSymbolAddress((void**)&qkv, g_qkv);
    cudaGetSymbolAddress((void**)&att, g_att);
    cudaGetSymbolAddress((void**)&mlp, g_mlp);
    cudaGetSymbolAddress((void**)&pw,  g_pw);
    cudaGetSymbolAddress((void**)&t,   g_t);
    cudaGetSymbolAddress((void**)&u,   g_u);

    const int ATTN_SMEM = 4 * 64 * 68 * 4;                        // 69632 B
    const int GEMM_SMEM_128 = (2*128*36 + 2*32*132) * 4;          // 70656 B
    const int GEMM_SMEM_64  = (2*64*36  + 2*32*132) * 4;          // 52224 B
    cudaFuncSetAttribute(attn_kernel, cudaFuncAttributeMaxDynamicSharedMemorySize, ATTN_SMEM);
    cudaFuncSetAttribute(gemm_tf32_kernel<128,false,false,false>,
                         cudaFuncAttributeMaxDynamicSharedMemorySize, GEMM_SMEM_128);
    cudaFuncSetAttribute(gemm_tf32_kernel<128,true,true,false>,
                         cudaFuncAttributeMaxDynamicSharedMemorySize, GEMM_SMEM_128);
    cudaFuncSetAttribute(gemm_tf32_kernel<64,false,true,true>,
                         cudaFuncAttributeMaxDynamicSharedMemorySize, GEMM_SMEM_64);

    // conv patch embed
    conv1_kernel<<<(Bn*256*2*Ln + 255)/256, 256>>>(img, conv1_w, conv1_b, c1);
    conv2_kernel<<<dim3(Ln/16, Bn), 256>>>(c1, conv2_w, conv2_b, c2);
    conv3_kernel<<<dim3(Ln/16, Bn), 256>>>(c2, conv3_w, conv3_b, x);

    for (int lyr = 0; lyr < DEPTHn; lyr++) {
        // attention block
        ln_kernel<<<ROWS, 256>>>(x, ln1_s + lyr*DIMn, ln1_b + lyr*DIMn, h);
        gemm_tf32_kernel<128,false,false,false><<<dim3(QKV3n/128, ROWS/128), 256, GEMM_SMEM_128>>>(
            h, qkv_w + (size_t)lyr*DIMn*QKV3n, nullptr, nullptr, qkv, ROWS, QKV3n, DIMn);
        attn_kernel<<<dim3(Ln/64, HEADSn, Bn), 128, ATTN_SMEM>>>(
            qkv, pos + (size_t)lyr*HEADSn*Ln*Ln, att);
        gemm_tf32_kernel<64,false,true,true><<<dim3(DIMn/128, ROWS/64), 256, GEMM_SMEM_64>>>(
            att, out_w + (size_t)lyr*INNERn*DIMn, out_b + lyr*DIMn, x, x, ROWS, DIMn, INNERn);
        // MLP block
        ln_kernel<<<ROWS, 256>>>(x, ln2_s + lyr*DIMn, ln2_b + lyr*DIMn, h);
        gemm_tf32_kernel<128,true,true,false><<<dim3(MLPn/128, ROWS/128), 256, GEMM_SMEM_128>>>(
            h, ff_w1 + (size_t)lyr*DIMn*MLPn, ff_b1 + lyr*MLPn, nullptr, mlp, ROWS, MLPn, DIMn);
        gemm_tf32_kernel<64,false,true,true><<<dim3(DIMn/128, ROWS/64), 256, GEMM_SMEM_64>>>(
            mlp, ff_w2 + (size_t)lyr*MLPn*DIMn, ff_b2 + lyr*DIMn, x, x, ROWS, DIMn, MLPn);
    }

    // SE attention pool
    meanpool_kernel<<<ROWS, 256>>>(x, pw);
    se1_kernel<<<1, 512>>>(pw, se_w1, se_b1, t);
    se2_kernel<<<(Bn*Ln)/256, 256>>>(t, se_w2, se_b2, u);
    pool_out_kernel<<<Bn, 256>>>(u, x, out);
}

// round 5
// speedup vs baseline: 6.7450x; 1.6828x over previous
#include <cuda_runtime.h>
#include <cuda_bf16.h>
#include <math.h>

// ---------------- problem constants ----------------
#define Bn    4
#define Ln    1024
#define DIMn  256
#define HEADSn 8
#define DHn   64
#define DEPTHn 2
#define MLPn  512
#define INNERn 512
#define QKV3n 1536
#define ROWS  (Bn*Ln)     // 4096
#define LP    1032        // padded length (idx 0 = l=-1, idx 1..1024 = l, idx 1025..1031 pad)

// ---------------- scratch (device globals; no allocs allowed) ----------------
__device__ float g_c1p[Bn*512*LP];      // conv1 out, padded [b][ch=ci*2+hh][LP]
__device__ float g_c2p[Bn*256*LP];      // conv2 out, padded [b][co][LP]
__device__ float g_w2t[256*1536];       // conv2 weights kk-major
__device__ float g_w3t[256*768];        // conv3 weights kk-major
__device__ float g_x [ROWS*DIMn];
__device__ float g_h [ROWS*DIMn];
__device__ float g_qkv[ROWS*QKV3n];
__device__ float g_att[ROWS*INNERn];
__device__ float g_mlp[ROWS*MLPn];
__device__ float g_pw[ROWS];
__device__ float g_t [Bn*128];
__device__ float g_u [Bn*Ln];

// ---------------- helpers: tf32 mma ----------------
__device__ __forceinline__ unsigned tf32_of(float f) {
    unsigned u; asm("cvt.rna.tf32.f32 %0, %1;" : "=r"(u) : "f"(f)); return u;
}
__device__ __forceinline__ void mma_tf32(float* c, const unsigned* a, const unsigned* b) {
    asm volatile("mma.sync.aligned.m16n8k8.row.col.f32.tf32.tf32.f32 "
        "{%0,%1,%2,%3}, {%4,%5,%6,%7}, {%8,%9}, {%0,%1,%2,%3};"
        : "+f"(c[0]), "+f"(c[1]), "+f"(c[2]), "+f"(c[3])
        : "r"(a[0]), "r"(a[1]), "r"(a[2]), "r"(a[3]), "r"(b[0]), "r"(b[1]));
}

// ---------------- conv1: 1->256, kernel (1,3), pad (0,1); writes padded ----------------
__global__ void conv1_kernel(const float* __restrict__ img, const float* __restrict__ w,
                             const float* __restrict__ bias, float* __restrict__ out)
{
    int idx = blockIdx.x * 256 + threadIdx.x;        // [b][c][hh][l]
    if (idx >= Bn*256*2*Ln) return;
    int l  = idx & (Ln-1);
    int hh = (idx >> 10) & 1;
    int c  = (idx >> 11) & 255;
    int b  = idx >> 19;
    const float* ir = img + ((size_t)b*2 + hh)*Ln;
    float acc = bias[c];
    #pragma unroll
    for (int k = 0; k < 3; k++) {
        int ll = l + k - 1;
        if (ll >= 0 && ll < Ln) acc += ir[ll] * w[c*3 + k];
    }
    out[((size_t)(b*512 + c*2 + hh))*LP + 1 + l] = fmaxf(acc, 0.f);
}

// zero pad columns of c1p (2048 rows) and c2p (1024 rows): idx 0 and 1025..1031
__global__ void pad_zero_kernel(float* __restrict__ c1p, float* __restrict__ c2p)
{
    int idx = blockIdx.x * 256 + threadIdx.x;
    if (idx < 2048*8) {
        int row = idx >> 3, p = idx & 7;
        int pos = (p == 0) ? 0 : 1024 + p;
        c1p[(size_t)row*LP + pos] = 0.f;
    } else if (idx < 2048*8 + 1024*8) {
        int i2 = idx - 2048*8;
        int row = i2 >> 3, p = i2 & 7;
        int pos = (p == 0) ? 0 : 1024 + p;
        c2p[(size_t)row*LP + pos] = 0.f;
    }
}

// weight reorder: [co][ch*3+kk] -> [co][kk*CIN+ch]
__global__ void wtrans_kernel(const float* __restrict__ w, float* __restrict__ wt,
                              int CIN, int total)
{
    int idx = blockIdx.x * 256 + threadIdx.x;
    if (idx >= total) return;
    int K = CIN * 3;
    int co = idx / K, rem = idx - co*K;
    int ch = rem / 3, kk = rem - ch*3;
    wt[(size_t)co*K + kk*CIN + ch] = w[idx];
}

// ---------------- conv as GEMM (2xtf32): C[co][l] = sum_{kk,ch} W[co][kk*CIN+ch] * in[ch][l+kk-1]
// BM=64, BN=128, 256 threads = 8 warps (WM=2, WN=4, warp tile 32x32, NT=4)
template<bool TRANSOUT>
__global__ __launch_bounds__(256)
void conv_gemm_kernel(const float* __restrict__ A, const float* __restrict__ inb,
                      const float* __restrict__ bias, float* __restrict__ Cout,
                      int K, int CIN)
{
    constexpr int BM = 64;
    constexpr int NT = 4;       // n-subtiles per warp (warp tile 32 cols)
    extern __shared__ unsigned smu[];
    unsigned* As_hi = smu;               // [64][36]
    unsigned* As_lo = smu + 64*36;
    unsigned* Bs    = smu + 2*64*36;     // [32][132]

    int tid = threadIdx.x;
    int warp = tid >> 5, lane = tid & 31;
    int g = lane >> 2, t = lane & 3;
    int wm = warp % 2, wn = warp / 2;
    int bm = blockIdx.y * BM, bn = blockIdx.x * 128;
    int b = blockIdx.z;
    const float* base = inb + (size_t)b * CIN * LP;

    float acc[2][NT][4];
    #pragma unroll
    for (int mt = 0; mt < 2; mt++)
        #pragma unroll
        for (int nt = 0; nt < NT; nt++)
            #pragma unroll
            for (int i = 0; i < 4; i++) acc[mt][nt][i] = 0.f;

    for (int k0 = 0; k0 < K; k0 += 32) {
        // stage A [64][32] hi/lo
        #pragma unroll
        for (int v = 0; v < 2; v++) {
            int slot = tid + 256*v;
            int r = slot >> 3, c4 = (slot & 7) * 4;
            float4 av = *(const float4*)&A[(size_t)(bm + r)*K + k0 + c4];
            unsigned h0 = tf32_of(av.x), h1 = tf32_of(av.y), h2 = tf32_of(av.z), h3 = tf32_of(av.w);
            *(uint4*)&As_hi[r*36 + c4] = make_uint4(h0, h1, h2, h3);
            *(uint4*)&As_lo[r*36 + c4] = make_uint4(
                tf32_of(av.x - __uint_as_float(h0)), tf32_of(av.y - __uint_as_float(h1)),
                tf32_of(av.z - __uint_as_float(h2)), tf32_of(av.w - __uint_as_float(h3)));
        }
        // stage B [32][128]: row r = k0+kr -> (kk, ch); value = in[ch][col + kk] (padded)
        #pragma unroll
        for (int v = 0; v < 4; v++) {
            int slot = tid + 256*v;
            int kr = slot >> 5, c4 = (slot & 31) * 4;
            int r = k0 + kr;
            int kk = r / CIN, ch = r - kk*CIN;
            const float* src = base + (size_t)ch*LP + bn + c4 + kk;
            Bs[kr*132 + c4 + 0] = tf32_of(src[0]);
            Bs[kr*132 + c4 + 1] = tf32_of(src[1]);
            Bs[kr*132 + c4 + 2] = tf32_of(src[2]);
            Bs[kr*132 + c4 + 3] = tf32_of(src[3]);
        }
        __syncthreads();
        #pragma unroll
        for (int kk = 0; kk < 4; kk++) {
            int kb = kk * 8;
            unsigned ah[2][4], al[2][4];
            #pragma unroll
            for (int mt = 0; mt < 2; mt++) {
                int m = wm*32 + mt*16;
                ah[mt][0] = As_hi[(m + g    )*36 + kb + t    ];
                ah[mt][1] = As_hi[(m + g + 8)*36 + kb + t    ];
                ah[mt][2] = As_hi[(m + g    )*36 + kb + t + 4];
                ah[mt][3] = As_hi[(m + g + 8)*36 + kb + t + 4];
                al[mt][0] = As_lo[(m + g    )*36 + kb + t    ];
                al[mt][1] = As_lo[(m + g + 8)*36 + kb + t    ];
                al[mt][2] = As_lo[(m + g    )*36 + kb + t + 4];
                al[mt][3] = As_lo[(m + g + 8)*36 + kb + t + 4];
            }
            #pragma unroll
            for (int nt = 0; nt < NT; nt++) {
                int n = wn*32 + nt*8 + g;
                unsigned bh[2];
                bh[0] = Bs[(kb + t    )*132 + n];
                bh[1] = Bs[(kb + t + 4)*132 + n];
                #pragma unroll
                for (int mt = 0; mt < 2; mt++) {
                    mma_tf32(acc[mt][nt], al[mt], bh);
                    mma_tf32(acc[mt][nt], ah[mt], bh);
                }
            }
        }
        __syncthreads();
    }
    #pragma unroll
    for (int mt = 0; mt < 2; mt++) {
        int r0 = bm + wm*32 + mt*16 + g;
        float b0 = bias[r0], b1 = bias[r0 + 8];
        #pragma unroll
        for (int nt = 0; nt < NT; nt++) {
            int col = bn + wn*32 + nt*8 + 2*t;
            float v00 = fmaxf(acc[mt][nt][0] + b0, 0.f);
            float v01 = fmaxf(acc[mt][nt][1] + b0, 0.f);
            float v10 = fmaxf(acc[mt][nt][2] + b1, 0.f);
            float v11 = fmaxf(acc[mt][nt][3] + b1, 0.f);
            if (TRANSOUT) {   // x[b][l=col][d=row]
                Cout[((size_t)b*Ln + col    )*DIMn + r0    ] = v00;
                Cout[((size_t)b*Ln + col + 1)*DIMn + r0    ] = v01;
                Cout[((size_t)b*Ln + col    )*DIMn + r0 + 8] = v10;
                Cout[((size_t)b*Ln + col + 1)*DIMn + r0 + 8] = v11;
            } else {          // padded [b][row][1+col]
                Cout[((size_t)b*256 + r0    )*LP + 1 + col    ] = v00;
                Cout[((size_t)b*256 + r0    )*LP + 1 + col + 1] = v01;
                Cout[((size_t)b*256 + r0 + 8)*LP + 1 + col    ] = v10;
                Cout[((size_t)b*256 + r0 + 8)*LP + 1 + col + 1] = v11;
            }
        }
    }
}

// ---------------- layernorm / mean pool: warp per row, shuffle reductions ----------------
__global__ void ln_kernel(const float* __restrict__ x, const float* __restrict__ s,
                          const float* __restrict__ b, float* __restrict__ out)
{
    int row = blockIdx.x*8 + (threadIdx.x >> 5);
    int lane = threadIdx.x & 31;
    const float* xr = x + (size_t)row*DIMn + lane*8;
    float4 a = *(const float4*)xr;
    float4 c = *(const float4*)(xr + 4);
    float sum = a.x+a.y+a.z+a.w + c.x+c.y+c.z+c.w;
    #pragma unroll
    for (int off = 16; off > 0; off >>= 1) sum += __shfl_xor_sync(0xffffffffu, sum, off);
    float mean = sum * (1.f/DIMn);
    float d0=a.x-mean, d1=a.y-mean, d2=a.z-mean, d3=a.w-mean;
    float d4=c.x-mean, d5=c.y-mean, d6=c.z-mean, d7=c.w-mean;
    float sq = d0*d0+d1*d1+d2*d2+d3*d3+d4*d4+d5*d5+d6*d6+d7*d7;
    #pragma unroll
    for (int off = 16; off > 0; off >>= 1) sq += __shfl_xor_sync(0xffffffffu, sq, off);
    float rs = rsqrtf(sq * (1.f/DIMn) + 1e-5f);
    float4 sv0 = *(const float4*)&s[lane*8], sv1 = *(const float4*)&s[lane*8+4];
    float4 bv0 = *(const float4*)&b[lane*8], bv1 = *(const float4*)&b[lane*8+4];
    float* o = out + (size_t)row*DIMn + lane*8;
    *(float4*)o       = make_float4(d0*rs*sv0.x+bv0.x, d1*rs*sv0.y+bv0.y, d2*rs*sv0.z+bv0.z, d3*rs*sv0.w+bv0.w);
    *(float4*)(o + 4) = make_float4(d4*rs*sv1.x+bv1.x, d5*rs*sv1.y+bv1.y, d6*rs*sv1.z+bv1.z, d7*rs*sv1.w+bv1.w);
}

__global__ void meanpool_kernel(const float* __restrict__ x, float* __restrict__ w)
{
    int row = blockIdx.x*8 + (threadIdx.x >> 5);
    int lane = threadIdx.x & 31;
    const float* xr = x + (size_t)row*DIMn + lane*8;
    float4 a = *(const float4*)xr;
    float4 c = *(const float4*)(xr + 4);
    float sum = a.x+a.y+a.z+a.w + c.x+c.y+c.z+c.w;
    #pragma unroll
    for (int off = 16; off > 0; off >>= 1) sum += __shfl_xor_sync(0xffffffffu, sum, off);
    if (lane == 0) w[row] = sum * (1.f/DIMn);
}

// ---------------- 2xtf32 tensor-core GEMM (A split hi/lo, B plain tf32) ----------------
// C = A[MxK] @ B[KxN] (+bias)(+gelu)(+resid). BN=128, 256 threads = 8 warps.
template<int BM, bool GELU, bool HASB, bool HASR>
__global__ __launch_bounds__(256)
void gemm_tf32_kernel(const float* __restrict__ A, const float* __restrict__ Bm,
                      const float* __restrict__ bias, const float* __restrict__ resid,
                      float* __restrict__ C, int M, int N, int K)
{
    constexpr int WM  = BM/32;
    constexpr int WN  = 8/WM;
    constexpr int WTN = 128/WN;
    constexpr int NT  = WTN/8;

    extern __shared__ unsigned smu[];
    unsigned* As_hi = smu;                       // [BM][36]
    unsigned* As_lo = smu + BM*36;
    unsigned* Bs    = smu + 2*BM*36;             // [32][132]

    int tid = threadIdx.x;
    int warp = tid >> 5, lane = tid & 31;
    int g = lane >> 2, t = lane & 3;
    int wm = warp % WM, wn = warp / WM;
    int bm = blockIdx.y * BM, bn = blockIdx.x * 128;

    float acc[2][NT][4];
    #pragma unroll
    for (int mt = 0; mt < 2; mt++)
        #pragma unroll
        for (int nt = 0; nt < NT; nt++)
            #pragma unroll
            for (int i = 0; i < 4; i++) acc[mt][nt][i] = 0.f;

    for (int k0 = 0; k0 < K; k0 += 32) {
        #pragma unroll
        for (int v = 0; v < BM/32; v++) {
            int slot = tid + 256*v;
            int r = slot >> 3, c4 = (slot & 7) * 4;
            float4 av = *(const float4*)&A[(size_t)(bm + r)*K + k0 + c4];
            unsigned h0 = tf32_of(av.x), h1 = tf32_of(av.y), h2 = tf32_of(av.z), h3 = tf32_of(av.w);
            *(uint4*)&As_hi[r*36 + c4] = make_uint4(h0, h1, h2, h3);
            *(uint4*)&As_lo[r*36 + c4] = make_uint4(
                tf32_of(av.x - __uint_as_float(h0)), tf32_of(av.y - __uint_as_float(h1)),
                tf32_of(av.z - __uint_as_float(h2)), tf32_of(av.w - __uint_as_float(h3)));
        }
        #pragma unroll
        for (int v = 0; v < 4; v++) {
            int slot = tid + 256*v;
            int kr = slot >> 5, c4 = (slot & 31) * 4;
            float4 bv = *(const float4*)&Bm[(size_t)(k0 + kr)*N + bn + c4];
            *(uint4*)&Bs[kr*132 + c4] = make_uint4(tf32_of(bv.x), tf32_of(bv.y),
                                                   tf32_of(bv.z), tf32_of(bv.w));
        }
        __syncthreads();
        #pragma unroll
        for (int kk = 0; kk < 4; kk++) {
            int kb = kk * 8;
            unsigned ah[2][4], al[2][4];
            #pragma unroll
            for (int mt = 0; mt < 2; mt++) {
                int m = wm*32 + mt*16;
                ah[mt][0] = As_hi[(m + g    )*36 + kb + t    ];
                ah[mt][1] = As_hi[(m + g + 8)*36 + kb + t    ];
                ah[mt][2] = As_hi[(m + g    )*36 + kb + t + 4];
                ah[mt][3] = As_hi[(m + g + 8)*36 + kb + t + 4];
                al[mt][0] = As_lo[(m + g    )*36 + kb + t    ];
                al[mt][1] = As_lo[(m + g + 8)*36 + kb + t    ];
                al[mt][2] = As_lo[(m + g    )*36 + kb + t + 4];
                al[mt][3] = As_lo[(m + g + 8)*36 + kb + t + 4];
            }
            #pragma unroll
            for (int nt = 0; nt < NT; nt++) {
                int n = wn*WTN + nt*8 + g;
                unsigned bh[2];
                bh[0] = Bs[(kb + t    )*132 + n];
                bh[1] = Bs[(kb + t + 4)*132 + n];
                #pragma unroll
                for (int mt = 0; mt < 2; mt++) {
                    mma_tf32(acc[mt][nt], al[mt], bh);   // lo*hi
                    mma_tf32(acc[mt][nt], ah[mt], bh);   // hi*hi
                }
            }
        }
        __syncthreads();
    }
    #pragma unroll
    for (int mt = 0; mt < 2; mt++) {
        int r0 = bm + wm*32 + mt*16 + g;
        #pragma unroll
        for (int nt = 0; nt < NT; nt++) {
            int col = bn + wn*WTN + nt*8 + 2*t;
            float2 v0 = make_float2(acc[mt][nt][0], acc[mt][nt][1]);
            float2 v1 = make_float2(acc[mt][nt][2], acc[mt][nt][3]);
            if (HASB) {
                float2 bb = *(const float2*)&bias[col];
                v0.x += bb.x; v0.y += bb.y; v1.x += bb.x; v1.y += bb.y;
            }
            if (GELU) {
                v0.x = 0.5f*v0.x*(1.f + erff(v0.x*0.70710678118f));
                v0.y = 0.5f*v0.y*(1.f + erff(v0.y*0.70710678118f));
                v1.x = 0.5f*v1.x*(1.f + erff(v1.x*0.70710678118f));
                v1.y = 0.5f*v1.y*(1.f + erff(v1.y*0.70710678118f));
            }
            if (HASR) {
                float2 r0v = *(const float2*)&resid[(size_t)r0*N + col];
                float2 r1v = *(const float2*)&resid[(size_t)(r0+8)*N + col];
                v0.x += r0v.x; v0.y += r0v.y; v1.x += r1v.x; v1.y += r1v.y;
            }
            *(float2*)&C[(size_t)r0*N + col]     = v0;
            *(float2*)&C[(size_t)(r0+8)*N + col] = v1;
        }
    }
}

// ---------------- flash attention with tf32 mma ----------------
__global__ __launch_bounds__(128, 3)
void attn_kernel(const float* __restrict__ qkv, const float* __restrict__ pos,
                 float* __restrict__ out)
{
    extern __shared__ unsigned smu[];
    unsigned* Qs = smu;                // [64][68]
    unsigned* Ks = smu + 64*68;        // [d][j]
    unsigned* Vs = smu + 2*64*68;      // [j][d]
    unsigned* Ps = smu + 3*64*68;      // [64][68]

    int bq = blockIdx.x, h = blockIdx.y, b = blockIdx.z;
    int i0 = bq * 64;
    int tid = threadIdx.x;
    int warp = tid >> 5, lane = tid & 31;
    int g = lane >> 2, t = lane & 3;
    int m0 = warp * 16;
    const float* base = qkv + (size_t)b * Ln * QKV3n;

    #pragma unroll
    for (int v = 0; v < 8; v++) {
        int f = tid + 128*v;
        int r = f >> 4, c4 = (f & 15) * 4;
        float4 qv = *(const float4*)&base[(size_t)(i0 + r)*QKV3n + h*64 + c4];
        *(uint4*)&Qs[r*68 + c4] = make_uint4(tf32_of(qv.x), tf32_of(qv.y), tf32_of(qv.z), tf32_of(qv.w));
    }

    float o[8][4];
    #pragma unroll
    for (int nt = 0; nt < 8; nt++)
        #pragma unroll
        for (int i = 0; i < 4; i++) o[nt][i] = 0.f;
    float mrow0 = -1e30f, mrow1 = -1e30f, lrow0 = 0.f, lrow1 = 0.f;

    const float* pr0 = pos + ((size_t)(h*Ln + i0 + m0 + g    ))*Ln;
    const float* pr1 = pos + ((size_t)(h*Ln + i0 + m0 + g + 8))*Ln;

    for (int jt = 0; jt < 16; jt++) {
        int j0 = jt * 64;
        __syncthreads();
        #pragma unroll
        for (int v = 0; v < 8; v++) {
            int f = tid + 128*v;
            int r = f >> 4, c4 = (f & 15) * 4;
            float4 kv = *(const float4*)&base[(size_t)(j0 + r)*QKV3n + INNERn + h*64 + c4];
            Ks[(c4+0)*68 + r] = tf32_of(kv.x);
            Ks[(c4+1)*68 + r] = tf32_of(kv.y);
            Ks[(c4+2)*68 + r] = tf32_of(kv.z);
            Ks[(c4+3)*68 + r] = tf32_of(kv.w);
            float4 vv = *(const float4*)&base[(size_t)(j0 + r)*QKV3n + 2*INNERn + h*64 + c4];
            *(uint4*)&Vs[r*68 + c4] = make_uint4(tf32_of(vv.x), tf32_of(vv.y), tf32_of(vv.z), tf32_of(vv.w));
        }
        __syncthreads();

        float sa[8][4];
        #pragma unroll
        for (int nt = 0; nt < 8; nt++)
            #pragma unroll
            for (int i = 0; i < 4; i++) sa[nt][i] = 0.f;
        #pragma unroll
        for (int kc = 0; kc < 8; kc++) {
            int kb = kc * 8;
            unsigned a[4];
            a[0] = Qs[(m0 + g    )*68 + kb + t    ];
            a[1] = Qs[(m0 + g + 8)*68 + kb + t    ];
            a[2] = Qs[(m0 + g    )*68 + kb + t + 4];
            a[3] = Qs[(m0 + g + 8)*68 + kb + t + 4];
            #pragma unroll
            for (int nt = 0; nt < 8; nt++) {
                unsigned bb[2];
                bb[0] = Ks[(kb + t    )*68 + nt*8 + g];
                bb[1] = Ks[(kb + t + 4)*68 + nt*8 + g];
                mma_tf32(sa[nt], a, bb);
            }
        }
        #pragma unroll
        for (int nt = 0; nt < 8; nt++) {
            float2 p0 = *(const float2*)&pr0[j0 + nt*8 + 2*t];
            float2 p1 = *(const float2*)&pr1[j0 + nt*8 + 2*t];
            sa[nt][0] = sa[nt][0]*0.125f + p0.x;
            sa[nt][1] = sa[nt][1]*0.125f + p0.y;
            sa[nt][2] = sa[nt][2]*0.125f + p1.x;
            sa[nt][3] = sa[nt][3]*0.125f + p1.y;
        }
        float mx0 = -1e30f, mx1 = -1e30f;
        #pragma unroll
        for (int nt = 0; nt < 8; nt++) {
            mx0 = fmaxf(mx0, fmaxf(sa[nt][0], sa[nt][1]));
            mx1 = fmaxf(mx1, fmaxf(sa[nt][2], sa[nt][3]));
        }
        mx0 = fmaxf(mx0, __shfl_xor_sync(0xffffffffu, mx0, 1));
        mx0 = fmaxf(mx0, __shfl_xor_sync(0xffffffffu, mx0, 2));
        mx1 = fmaxf(mx1, __shfl_xor_sync(0xffffffffu, mx1, 1));
        mx1 = fmaxf(mx1, __shfl_xor_sync(0xffffffffu, mx1, 2));
        float mn0 = fmaxf(mrow0, mx0), mn1 = fmaxf(mrow1, mx1);
        float corr0 = expf(mrow0 - mn0), corr1 = expf(mrow1 - mn1);
        float ts0 = 0.f, ts1 = 0.f;
        #pragma unroll
        for (int nt = 0; nt < 8; nt++) {
            float e0 = expf(sa[nt][0] - mn0);
            float e1 = expf(sa[nt][1] - mn0);
            float e2 = expf(sa[nt][2] - mn1);
            float e3 = expf(sa[nt][3] - mn1);
            ts0 += e0 + e1; ts1 += e2 + e3;
            int c = nt*8 + 2*t;
            Ps[(m0 + g    )*68 + c    ] = tf32_of(e0);
            Ps[(m0 + g    )*68 + c + 1] = tf32_of(e1);
            Ps[(m0 + g + 8)*68 + c    ] = tf32_of(e2);
            Ps[(m0 + g + 8)*68 + c + 1] = tf32_of(e3);
        }
        ts0 += __shfl_xor_sync(0xffffffffu, ts0, 1);
        ts0 += __shfl_xor_sync(0xffffffffu, ts0, 2);
        ts1 += __shfl_xor_sync(0xffffffffu, ts1, 1);
        ts1 += __shfl_xor_sync(0xffffffffu, ts1, 2);
        lrow0 = lrow0*corr0 + ts0;
        lrow1 = lrow1*corr1 + ts1;
        mrow0 = mn0; mrow1 = mn1;
        #pragma unroll
        for (int nt = 0; nt < 8; nt++) {
            o[nt][0] *= corr0; o[nt][1] *= corr0;
            o[nt][2] *= corr1; o[nt][3] *= corr1;
        }
        __syncwarp();
        #pragma unroll
        for (int kc = 0; kc < 8; kc++) {
            int kb = kc * 8;
            unsigned a[4];
            a[0] = Ps[(m0 + g    )*68 + kb + t    ];
            a[1] = Ps[(m0 + g + 8)*68 + kb + t    ];
            a[2] = Ps[(m0 + g    )*68 + kb + t + 4];
            a[3] = Ps[(m0 + g + 8)*68 + kb + t + 4];
            #pragma unroll
            for (int nt = 0; nt < 8; nt++) {
                unsigned bb[2];
                bb[0] = Vs[(kb + t    )*68 + nt*8 + g];
                bb[1] = Vs[(kb + t + 4)*68 + nt*8 + g];
                mma_tf32(o[nt], a, bb);
            }
        }
    }
    float inv0 = 1.f / lrow0, inv1 = 1.f / lrow1;
    size_t r0 = (size_t)b*Ln + i0 + m0 + g;
    size_t r1 = r0 + 8;
    #pragma unroll
    for (int nt = 0; nt < 8; nt++) {
        int col = h*64 + nt*8 + 2*t;
        *(float2*)&out[r0*INNERn + col] = make_float2(o[nt][0]*inv0, o[nt][1]*inv0);
        *(float2*)&out[r1*INNERn + col] = make_float2(o[nt][2]*inv1, o[nt][3]*inv1);
    }
}

// ---------------- SE pool tail ----------------
__global__ void se1_kernel(const float* __restrict__ wv, const float* __restrict__ w1,
                           const float* __restrict__ b1, float* __restrict__ t)
{
    int tid = threadIdx.x;                            // 512
    int b = tid >> 7, j = tid & 127;
    float acc = b1[j];
    for (int l = 0; l < Ln; l++) acc += wv[b*Ln + l] * w1[l*128 + j];
    t[tid] = fmaxf(acc, 0.f);
}

__global__ void se2_kernel(const float* __restrict__ t, const float* __restrict__ w2,
                           const float* __restrict__ b2, float* __restrict__ u)
{
    int idx = blockIdx.x * 256 + threadIdx.x;         // 4096
    int b = idx >> 10, l = idx & (Ln-1);
    float acc = b2[l];
    #pragma unroll
    for (int j = 0; j < 128; j++) acc += t[b*128 + j] * w2[j*Ln + l];
    u[idx] = 1.f / (1.f + expf(-acc));
}

__global__ void pool_out_kernel(const float* __restrict__ u, const float* __restrict__ x,
                                float* __restrict__ out)
{
    int b = blockIdx.x, d = threadIdx.x;              // 4 x 256
    float acc = 0.f;
    for (int l = 0; l < Ln; l++) acc += u[b*Ln + l] * x[((size_t)b*Ln + l)*DIMn + d];
    out[b*DIMn + d] = acc;
}

// ---------------- host launch ----------------
extern "C" void kernel_launch(void* const* d_in, const int* in_sizes, int n_in,
                              void* d_out, int out_size)
{
    const float* img     = (const float*)d_in[0];
    const float* conv1_w = (const float*)d_in[1];
    const float* conv1_b = (const float*)d_in[2];
    const float* conv2_w = (const float*)d_in[3];
    const float* conv2_b = (const float*)d_in[4];
    const float* conv3_w = (const float*)d_in[5];
    const float* conv3_b = (const float*)d_in[6];
    const float* ln1_s   = (const float*)d_in[7];
    const float* ln1_b   = (const float*)d_in[8];
    const float* qkv_w   = (const float*)d_in[9];
    const float* pos     = (const float*)d_in[10];
    const float* out_w   = (const float*)d_in[11];
    const float* out_b   = (const float*)d_in[12];
    const float* ln2_s   = (const float*)d_in[13];
    const float* ln2_b   = (const float*)d_in[14];
    const float* ff_w1   = (const float*)d_in[15];
    const float* ff_b1   = (const float*)d_in[16];
    const float* ff_w2   = (const float*)d_in[17];
    const float* ff_b2   = (const float*)d_in[18];
    const float* se_w1   = (const float*)d_in[19];
    const float* se_b1   = (const float*)d_in[20];
    const float* se_w2   = (const float*)d_in[21];
    const float* se_b2   = (const float*)d_in[22];
    float* out = (float*)d_out;

    float *c1p, *c2p, *w2t, *w3t, *x, *h, *qkv, *att, *mlp, *pw, *t, *u;
    cudaGetSymbolAddress((void**)&c1p, g_c1p);
    cudaGetSymbolAddress((void**)&c2p, g_c2p);
    cudaGetSymbolAddress((void**)&w2t, g_w2t);
    cudaGetSymbolAddress((void**)&w3t, g_w3t);
    cudaGetSymbolAddress((void**)&x,   g_x);
    cudaGetSymbolAddress((void**)&h,   g_h);
    cudaGetSymbolAddress((void**)&qkv, g_qkv);
    cudaGetSymbolAddress((void**)&att, g_att);
    cudaGetSymbolAddress((void**)&mlp, g_mlp);
    cudaGetSymbolAddress((void**)&pw,  g_pw);
    cudaGetSymbolAddress((void**)&t,   g_t);
    cudaGetSymbolAddress((void**)&u,   g_u);

    const int ATTN_SMEM = 4 * 64 * 68 * 4;                 // 69632 B
    const int GEMM_SMEM_128 = (2*128*36 + 32*132) * 4;     // 53760 B
    const int GEMM_SMEM_64  = (2*64*36  + 32*132) * 4;     // 35328 B
    const int CG_SMEM       = GEMM_SMEM_64;
    cudaFuncSetAttribute(attn_kernel, cudaFuncAttributeMaxDynamicSharedMemorySize, ATTN_SMEM);
    cudaFuncSetAttribute(gemm_tf32_kernel<128,false,false,false>,
                         cudaFuncAttributeMaxDynamicSharedMemorySize, GEMM_SMEM_128);
    cudaFuncSetAttribute(gemm_tf32_kernel<128,true,true,false>,
                         cudaFuncAttributeMaxDynamicSharedMemorySize, GEMM_SMEM_128);
    cudaFuncSetAttribute(gemm_tf32_kernel<64,false,true,true>,
                         cudaFuncAttributeMaxDynamicSharedMemorySize, GEMM_SMEM_64);

    // conv patch embed (conv2/conv3 as shifted tensor-core GEMMs)
    conv1_kernel<<<(Bn*256*2*Ln + 255)/256, 256>>>(img, conv1_w, conv1_b, c1p);
    pad_zero_kernel<<<(2048*8 + 1024*8 + 255)/256, 256>>>(c1p, c2p);
    wtrans_kernel<<<(256*1536 + 255)/256, 256>>>(conv2_w, w2t, 512, 256*1536);
    wtrans_kernel<<<(256*768  + 255)/256, 256>>>(conv3_w, w3t, 256, 256*768);
    conv_gemm_kernel<false><<<dim3(8, 4, Bn), 256, CG_SMEM>>>(w2t, c1p, conv2_b, c2p, 1536, 512);
    conv_gemm_kernel<true ><<<dim3(8, 4, Bn), 256, CG_SMEM>>>(w3t, c2p, conv3_b, x,   768,  256);

    for (int lyr = 0; lyr < DEPTHn; lyr++) {
        // attention block
        ln_kernel<<<ROWS/8, 256>>>(x, ln1_s + lyr*DIMn, ln1_b + lyr*DIMn, h);
        gemm_tf32_kernel<128,false,false,false><<<dim3(QKV3n/128, ROWS/128), 256, GEMM_SMEM_128>>>(
            h, qkv_w + (size_t)lyr*DIMn*QKV3n, nullptr, nullptr, qkv, ROWS, QKV3n, DIMn);
        attn_kernel<<<dim3(Ln/64, HEADSn, Bn), 128, ATTN_SMEM>>>(
            qkv, pos + (size_t)lyr*HEADSn*Ln*Ln, att);
        gemm_tf32_kernel<64,false,true,true><<<dim3(DIMn/128, ROWS/64), 256, GEMM_SMEM_64>>>(
            att, out_w + (size_t)lyr*INNERn*DIMn, out_b + lyr*DIMn, x, x, ROWS, DIMn, INNERn);
        // MLP block
        ln_kernel<<<ROWS/8, 256>>>(x, ln2_s + lyr*DIMn, ln2_b + lyr*DIMn, h);
        gemm_tf32_kernel<128,true,true,false><<<dim3(MLPn/128, ROWS/128), 256, GEMM_SMEM_128>>>(
            h, ff_w1 + (size_t)lyr*DIMn*MLPn, ff_b1 + lyr*MLPn, nullptr, mlp, ROWS, MLPn, DIMn);
        gemm_tf32_kernel<64,false,true,true><<<dim3(DIMn/128, ROWS/64), 256, GEMM_SMEM_64>>>(
            mlp, ff_w2 + (size_t)lyr*MLPn*DIMn, ff_b2 + lyr*DIMn, x, x, ROWS, DIMn, MLPn);
    }

    // SE attention pool
    meanpool_kernel<<<ROWS/8, 256>>>(x, pw);
    se1_kernel<<<1, 512>>>(pw, se_w1, se_b1, t);
    se2_kernel<<<(Bn*Ln)/256, 256>>>(t, se_w2, se_b2, u);
    pool_out_kernel<<<Bn, 256>>>(u, x, out);
}

// round 6
// speedup vs baseline: 8.0720x; 1.1967x over previous
#include <cuda_runtime.h>
#include <cuda_bf16.h>
#include <math.h>

// ---------------- problem constants ----------------
#define Bn    4
#define Ln    1024
#define DIMn  256
#define HEADSn 8
#define DHn   64
#define DEPTHn 2
#define MLPn  512
#define INNERn 512
#define QKV3n 1536
#define ROWS  (Bn*Ln)     // 4096
#define LP    1032        // padded length (idx 0 = l=-1, idx 1..1024 = l, idx 1025..1031 pad)

// ---------------- scratch (device globals; no allocs allowed) ----------------
__device__ float g_c1p[Bn*512*LP];
__device__ float g_c2p[Bn*256*LP];
__device__ float g_w2t[256*1536];
__device__ float g_w3t[256*768];
__device__ float g_x [ROWS*DIMn];
__device__ float g_qkv[ROWS*QKV3n];
__device__ float g_att[ROWS*INNERn];
__device__ float g_mlp[ROWS*MLPn];
__device__ float g_m [ROWS];
__device__ float g_r [ROWS];
__device__ float g_pw[ROWS];
__device__ float g_t [Bn*128];
__device__ float g_u [Bn*Ln];

// ---------------- helpers: tf32 mma ----------------
__device__ __forceinline__ unsigned tf32_of(float f) {
    unsigned u; asm("cvt.rna.tf32.f32 %0, %1;" : "=r"(u) : "f"(f)); return u;
}
__device__ __forceinline__ void mma_tf32(float* c, const unsigned* a, const unsigned* b) {
    asm volatile("mma.sync.aligned.m16n8k8.row.col.f32.tf32.tf32.f32 "
        "{%0,%1,%2,%3}, {%4,%5,%6,%7}, {%8,%9}, {%0,%1,%2,%3};"
        : "+f"(c[0]), "+f"(c[1]), "+f"(c[2]), "+f"(c[3])
        : "r"(a[0]), "r"(a[1]), "r"(a[2]), "r"(a[3]), "r"(b[0]), "r"(b[1]));
}

// ---------------- conv1: 1->256, kernel (1,3), pad (0,1); writes padded ----------------
__global__ void conv1_kernel(const float* __restrict__ img, const float* __restrict__ w,
                             const float* __restrict__ bias, float* __restrict__ out)
{
    int idx = blockIdx.x * 256 + threadIdx.x;
    if (idx >= Bn*256*2*Ln) return;
    int l  = idx & (Ln-1);
    int hh = (idx >> 10) & 1;
    int c  = (idx >> 11) & 255;
    int b  = idx >> 19;
    const float* ir = img + ((size_t)b*2 + hh)*Ln;
    float acc = bias[c];
    #pragma unroll
    for (int k = 0; k < 3; k++) {
        int ll = l + k - 1;
        if (ll >= 0 && ll < Ln) acc += ir[ll] * w[c*3 + k];
    }
    out[((size_t)(b*512 + c*2 + hh))*LP + 1 + l] = fmaxf(acc, 0.f);
}

__global__ void pad_zero_kernel(float* __restrict__ c1p, float* __restrict__ c2p)
{
    int idx = blockIdx.x * 256 + threadIdx.x;
    if (idx < 2048*8) {
        int row = idx >> 3, p = idx & 7;
        int pos = (p == 0) ? 0 : 1024 + p;
        c1p[(size_t)row*LP + pos] = 0.f;
    } else if (idx < 2048*8 + 1024*8) {
        int i2 = idx - 2048*8;
        int row = i2 >> 3, p = i2 & 7;
        int pos = (p == 0) ? 0 : 1024 + p;
        c2p[(size_t)row*LP + pos] = 0.f;
    }
}

__global__ void wtrans_kernel(const float* __restrict__ w, float* __restrict__ wt,
                              int CIN, int total)
{
    int idx = blockIdx.x * 256 + threadIdx.x;
    if (idx >= total) return;
    int K = CIN * 3;
    int co = idx / K, rem = idx - co*K;
    int ch = rem / 3, kk = rem - ch*3;
    wt[(size_t)co*K + kk*CIN + ch] = w[idx];
}

// ---------------- conv as GEMM (2xtf32), software-pipelined ----------------
// C[co][l] = sum_{kk,ch} W[co][kk*CIN+ch] * in[ch][l+kk-1]; BM=64, BN=128.
template<bool TRANSOUT>
__global__ __launch_bounds__(256)
void conv_gemm_kernel(const float* __restrict__ A, const float* __restrict__ inb,
                      const float* __restrict__ bias, float* __restrict__ Cout,
                      int K, int CIN, int cinlog)
{
    constexpr int BM = 64;
    constexpr int NT = 4;
    constexpr int BUFU = 2*BM*36 + 32*132;   // 8832 words
    extern __shared__ unsigned smu[];

    int tid = threadIdx.x;
    int warp = tid >> 5, lane = tid & 31;
    int g = lane >> 2, t = lane & 3;
    int wm = warp % 2, wn = warp / 2;
    int bm = blockIdx.y * BM, bn = blockIdx.x * 128;
    int b = blockIdx.z;
    const float* base = inb + (size_t)b * CIN * LP;

    float acc[2][NT][4];
    #pragma unroll
    for (int mt = 0; mt < 2; mt++)
        #pragma unroll
        for (int nt = 0; nt < NT; nt++)
            #pragma unroll
            for (int i = 0; i < 4; i++) acc[mt][nt][i] = 0.f;

    float4 pa[2], pb[4];

    auto LDG_TILE = [&](int k0) {
        #pragma unroll
        for (int v = 0; v < 2; v++) {
            int slot = tid + 256*v;
            int r = slot >> 3, c4 = (slot & 7) * 4;
            pa[v] = *(const float4*)&A[(size_t)(bm + r)*K + k0 + c4];
        }
        #pragma unroll
        for (int v = 0; v < 4; v++) {
            int slot = tid + 256*v;
            int kr = slot >> 5, c4 = (slot & 31) * 4;
            int rr = k0 + kr;
            int kk = rr >> cinlog, ch = rr - (kk << cinlog);
            const float* src = base + (size_t)ch*LP + bn + c4 + kk;
            pb[v] = make_float4(src[0], src[1], src[2], src[3]);
        }
    };
    auto STS_TILE = [&](int buf) {
        unsigned* Ah = smu + buf*BUFU;
        unsigned* Al = Ah + BM*36;
        unsigned* Bs = Ah + 2*BM*36;
        #pragma unroll
        for (int v = 0; v < 2; v++) {
            int slot = tid + 256*v;
            int r = slot >> 3, c4 = (slot & 7) * 4;
            float4 av = pa[v];
            unsigned h0 = tf32_of(av.x), h1 = tf32_of(av.y), h2 = tf32_of(av.z), h3 = tf32_of(av.w);
            *(uint4*)&Ah[r*36 + c4] = make_uint4(h0, h1, h2, h3);
            *(uint4*)&Al[r*36 + c4] = make_uint4(
                tf32_of(av.x - __uint_as_float(h0)), tf32_of(av.y - __uint_as_float(h1)),
                tf32_of(av.z - __uint_as_float(h2)), tf32_of(av.w - __uint_as_float(h3)));
        }
        #pragma unroll
        for (int v = 0; v < 4; v++) {
            int slot = tid + 256*v;
            int kr = slot >> 5, c4 = (slot & 31) * 4;
            *(uint4*)&Bs[kr*132 + c4] = make_uint4(tf32_of(pb[v].x), tf32_of(pb[v].y),
                                                   tf32_of(pb[v].z), tf32_of(pb[v].w));
        }
    };

    int nT = K / 32;
    LDG_TILE(0);
    STS_TILE(0);
    int cur = 0;
    for (int tt = 0; tt < nT; tt++) {
        if (tt + 1 < nT) LDG_TILE((tt+1)*32);
        __syncthreads();
        unsigned* Ah = smu + cur*BUFU;
        unsigned* Al = Ah + BM*36;
        unsigned* Bs = Ah + 2*BM*36;
        #pragma unroll
        for (int kk = 0; kk < 4; kk++) {
            int kb = kk * 8;
            unsigned ah[2][4], al[2][4];
            #pragma unroll
            for (int mt = 0; mt < 2; mt++) {
                int m = wm*32 + mt*16;
                ah[mt][0] = Ah[(m + g    )*36 + kb + t    ];
                ah[mt][1] = Ah[(m + g + 8)*36 + kb + t    ];
                ah[mt][2] = Ah[(m + g    )*36 + kb + t + 4];
                ah[mt][3] = Ah[(m + g + 8)*36 + kb + t + 4];
                al[mt][0] = Al[(m + g    )*36 + kb + t    ];
                al[mt][1] = Al[(m + g + 8)*36 + kb + t    ];
                al[mt][2] = Al[(m + g    )*36 + kb + t + 4];
                al[mt][3] = Al[(m + g + 8)*36 + kb + t + 4];
            }
            #pragma unroll
            for (int nt = 0; nt < NT; nt++) {
                int n = wn*32 + nt*8 + g;
                unsigned bh[2];
                bh[0] = Bs[(kb + t    )*132 + n];
                bh[1] = Bs[(kb + t + 4)*132 + n];
                #pragma unroll
                for (int mt = 0; mt < 2; mt++) {
                    mma_tf32(acc[mt][nt], al[mt], bh);
                    mma_tf32(acc[mt][nt], ah[mt], bh);
                }
            }
        }
        if (tt + 1 < nT) STS_TILE(cur ^ 1);
        cur ^= 1;
    }
    #pragma unroll
    for (int mt = 0; mt < 2; mt++) {
        int r0 = bm + wm*32 + mt*16 + g;
        float b0 = bias[r0], b1 = bias[r0 + 8];
        #pragma unroll
        for (int nt = 0; nt < NT; nt++) {
            int col = bn + wn*32 + nt*8 + 2*t;
            float v00 = fmaxf(acc[mt][nt][0] + b0, 0.f);
            float v01 = fmaxf(acc[mt][nt][1] + b0, 0.f);
            float v10 = fmaxf(acc[mt][nt][2] + b1, 0.f);
            float v11 = fmaxf(acc[mt][nt][3] + b1, 0.f);
            if (TRANSOUT) {
                Cout[((size_t)b*Ln + col    )*DIMn + r0    ] = v00;
                Cout[((size_t)b*Ln + col + 1)*DIMn + r0    ] = v01;
                Cout[((size_t)b*Ln + col    )*DIMn + r0 + 8] = v10;
                Cout[((size_t)b*Ln + col + 1)*DIMn + r0 + 8] = v11;
            } else {
                Cout[((size_t)b*256 + r0    )*LP + 1 + col    ] = v00;
                Cout[((size_t)b*256 + r0    )*LP + 1 + col + 1] = v01;
                Cout[((size_t)b*256 + r0 + 8)*LP + 1 + col    ] = v10;
                Cout[((size_t)b*256 + r0 + 8)*LP + 1 + col + 1] = v11;
            }
        }
    }
}

// ---------------- row stats (mean + rstd) / mean pool: warp per row ----------------
__global__ void rowstat_kernel(const float* __restrict__ x, float* __restrict__ mean,
                               float* __restrict__ rstd)
{
    int row = blockIdx.x*8 + (threadIdx.x >> 5);
    int lane = threadIdx.x & 31;
    const float* xr = x + (size_t)row*DIMn + lane*8;
    float4 a = *(const float4*)xr;
    float4 c = *(const float4*)(xr + 4);
    float sum = a.x+a.y+a.z+a.w + c.x+c.y+c.z+c.w;
    #pragma unroll
    for (int off = 16; off > 0; off >>= 1) sum += __shfl_xor_sync(0xffffffffu, sum, off);
    float m = sum * (1.f/DIMn);
    float d0=a.x-m, d1=a.y-m, d2=a.z-m, d3=a.w-m;
    float d4=c.x-m, d5=c.y-m, d6=c.z-m, d7=c.w-m;
    float sq = d0*d0+d1*d1+d2*d2+d3*d3+d4*d4+d5*d5+d6*d6+d7*d7;
    #pragma unroll
    for (int off = 16; off > 0; off >>= 1) sq += __shfl_xor_sync(0xffffffffu, sq, off);
    if (lane == 0) {
        mean[row] = m;
        rstd[row] = rsqrtf(sq * (1.f/DIMn) + 1e-5f);
    }
}

__global__ void meanpool_kernel(const float* __restrict__ x, float* __restrict__ w)
{
    int row = blockIdx.x*8 + (threadIdx.x >> 5);
    int lane = threadIdx.x & 31;
    const float* xr = x + (size_t)row*DIMn + lane*8;
    float4 a = *(const float4*)xr;
    float4 c = *(const float4*)(xr + 4);
    float sum = a.x+a.y+a.z+a.w + c.x+c.y+c.z+c.w;
    #pragma unroll
    for (int off = 16; off > 0; off >>= 1) sum += __shfl_xor_sync(0xffffffffu, sum, off);
    if (lane == 0) w[row] = sum * (1.f/DIMn);
}

// ---------------- 2xtf32 GEMM, software-pipelined, optional fused layernorm on A --------
template<int BM, bool GELU, bool HASB, bool HASR, bool LNA>
__global__ __launch_bounds__(256)
void gemm_tf32_kernel(const float* __restrict__ A, const float* __restrict__ Bm,
                      const float* __restrict__ bias, const float* __restrict__ resid,
                      float* __restrict__ C, int M, int N, int K,
                      const float* __restrict__ lnm, const float* __restrict__ lnr,
                      const float* __restrict__ lns, const float* __restrict__ lnb)
{
    constexpr int WM  = BM/32;
    constexpr int WN  = 8/WM;
    constexpr int WTN = 128/WN;
    constexpr int NT  = WTN/8;
    constexpr int AV  = BM/32;
    constexpr int BUFU = 2*BM*36 + 32*132;
    extern __shared__ unsigned smu[];

    int tid = threadIdx.x;
    int warp = tid >> 5, lane = tid & 31;
    int g = lane >> 2, t = lane & 3;
    int wm = warp % WM, wn = warp / WM;
    int bm = blockIdx.y * BM, bn = blockIdx.x * 128;

    float acc[2][NT][4];
    #pragma unroll
    for (int mt = 0; mt < 2; mt++)
        #pragma unroll
        for (int nt = 0; nt < NT; nt++)
            #pragma unroll
            for (int i = 0; i < 4; i++) acc[mt][nt][i] = 0.f;

    float4 pa[AV], pb[4];
    float pm[AV], pr[AV];    // per-row LN stats (rows fixed across tiles)

    if (LNA) {
        #pragma unroll
        for (int v = 0; v < AV; v++) {
            int slot = tid + 256*v;
            int r = slot >> 3;
            pm[v] = lnm[bm + r];
            pr[v] = lnr[bm + r];
        }
    }

    auto LDG_TILE = [&](int k0) {
        #pragma unroll
        for (int v = 0; v < AV; v++) {
            int slot = tid + 256*v;
            int r = slot >> 3, c4 = (slot & 7) * 4;
            pa[v] = *(const float4*)&A[(size_t)(bm + r)*K + k0 + c4];
        }
        #pragma unroll
        for (int v = 0; v < 4; v++) {
            int slot = tid + 256*v;
            int kr = slot >> 5, c4 = (slot & 31) * 4;
            pb[v] = *(const float4*)&Bm[(size_t)(k0 + kr)*N + bn + c4];
        }
    };
    auto STS_TILE = [&](int buf, int k0) {
        unsigned* Ah = smu + buf*BUFU;
        unsigned* Al = Ah + BM*36;
        unsigned* Bs = Ah + 2*BM*36;
        #pragma unroll
        for (int v = 0; v < AV; v++) {
            int slot = tid + 256*v;
            int r = slot >> 3, c4 = (slot & 7) * 4;
            float4 av = pa[v];
            if (LNA) {
                float4 s4 = *(const float4*)&lns[k0 + c4];
                float4 b4 = *(const float4*)&lnb[k0 + c4];
                float mm = pm[v], rs = pr[v];
                av.x = (av.x - mm)*rs*s4.x + b4.x;
                av.y = (av.y - mm)*rs*s4.y + b4.y;
                av.z = (av.z - mm)*rs*s4.z + b4.z;
                av.w = (av.w - mm)*rs*s4.w + b4.w;
            }
            unsigned h0 = tf32_of(av.x), h1 = tf32_of(av.y), h2 = tf32_of(av.z), h3 = tf32_of(av.w);
            *(uint4*)&Ah[r*36 + c4] = make_uint4(h0, h1, h2, h3);
            *(uint4*)&Al[r*36 + c4] = make_uint4(
                tf32_of(av.x - __uint_as_float(h0)), tf32_of(av.y - __uint_as_float(h1)),
                tf32_of(av.z - __uint_as_float(h2)), tf32_of(av.w - __uint_as_float(h3)));
        }
        #pragma unroll
        for (int v = 0; v < 4; v++) {
            int slot = tid + 256*v;
            int kr = slot >> 5, c4 = (slot & 31) * 4;
            *(uint4*)&Bs[kr*132 + c4] = make_uint4(tf32_of(pb[v].x), tf32_of(pb[v].y),
                                                   tf32_of(pb[v].z), tf32_of(pb[v].w));
        }
    };

    int nT = K / 32;
    LDG_TILE(0);
    STS_TILE(0, 0);
    int cur = 0;
    for (int tt = 0; tt < nT; tt++) {
        if (tt + 1 < nT) LDG_TILE((tt+1)*32);
        __syncthreads();
        unsigned* Ah = smu + cur*BUFU;
        unsigned* Al = Ah + BM*36;
        unsigned* Bs = Ah + 2*BM*36;
        #pragma unroll
        for (int kk = 0; kk < 4; kk++) {
            int kb = kk * 8;
            unsigned ah[2][4], al[2][4];
            #pragma unroll
            for (int mt = 0; mt < 2; mt++) {
                int m = wm*32 + mt*16;
                ah[mt][0] = Ah[(m + g    )*36 + kb + t    ];
                ah[mt][1] = Ah[(m + g + 8)*36 + kb + t    ];
                ah[mt][2] = Ah[(m + g    )*36 + kb + t + 4];
                ah[mt][3] = Ah[(m + g + 8)*36 + kb + t + 4];
                al[mt][0] = Al[(m + g    )*36 + kb + t    ];
                al[mt][1] = Al[(m + g + 8)*36 + kb + t    ];
                al[mt][2] = Al[(m + g    )*36 + kb + t + 4];
                al[mt][3] = Al[(m + g + 8)*36 + kb + t + 4];
            }
            #pragma unroll
            for (int nt = 0; nt < NT; nt++) {
                int n = wn*WTN + nt*8 + g;
                unsigned bh[2];
                bh[0] = Bs[(kb + t    )*132 + n];
                bh[1] = Bs[(kb + t + 4)*132 + n];
                #pragma unroll
                for (int mt = 0; mt < 2; mt++) {
                    mma_tf32(acc[mt][nt], al[mt], bh);
                    mma_tf32(acc[mt][nt], ah[mt], bh);
                }
            }
        }
        if (tt + 1 < nT) STS_TILE(cur ^ 1, (tt+1)*32);
        cur ^= 1;
    }
    #pragma unroll
    for (int mt = 0; mt < 2; mt++) {
        int r0 = bm + wm*32 + mt*16 + g;
        #pragma unroll
        for (int nt = 0; nt < NT; nt++) {
            int col = bn + wn*WTN + nt*8 + 2*t;
            float2 v0 = make_float2(acc[mt][nt][0], acc[mt][nt][1]);
            float2 v1 = make_float2(acc[mt][nt][2], acc[mt][nt][3]);
            if (HASB) {
                float2 bb = *(const float2*)&bias[col];
                v0.x += bb.x; v0.y += bb.y; v1.x += bb.x; v1.y += bb.y;
            }
            if (GELU) {
                v0.x = 0.5f*v0.x*(1.f + erff(v0.x*0.70710678118f));
                v0.y = 0.5f*v0.y*(1.f + erff(v0.y*0.70710678118f));
                v1.x = 0.5f*v1.x*(1.f + erff(v1.x*0.70710678118f));
                v1.y = 0.5f*v1.y*(1.f + erff(v1.y*0.70710678118f));
            }
            if (HASR) {
                float2 r0v = *(const float2*)&resid[(size_t)r0*N + col];
                float2 r1v = *(const float2*)&resid[(size_t)(r0+8)*N + col];
                v0.x += r0v.x; v0.y += r0v.y; v1.x += r1v.x; v1.y += r1v.y;
            }
            *(float2*)&C[(size_t)r0*N + col]     = v0;
            *(float2*)&C[(size_t)(r0+8)*N + col] = v1;
        }
    }
}

// ---------------- flash attention with tf32 mma ----------------
__global__ __launch_bounds__(128, 3)
void attn_kernel(const float* __restrict__ qkv, const float* __restrict__ pos,
                 float* __restrict__ out)
{
    extern __shared__ unsigned smu[];
    unsigned* Qs = smu;                // [m][d]
    unsigned* Ks = smu + 64*68;        // [j][d]  natural
    unsigned* Vs = smu + 2*64*68;      // [j][d]
    unsigned* Ps = smu + 3*64*68;      // [m][j]

    int bq = blockIdx.x, h = blockIdx.y, b = blockIdx.z;
    int i0 = bq * 64;
    int tid = threadIdx.x;
    int warp = tid >> 5, lane = tid & 31;
    int g = lane >> 2, t = lane & 3;
    int m0 = warp * 16;
    const float* base = qkv + (size_t)b * Ln * QKV3n;

    #pragma unroll
    for (int v = 0; v < 8; v++) {
        int f = tid + 128*v;
        int r = f >> 4, c4 = (f & 15) * 4;
        float4 qv = *(const float4*)&base[(size_t)(i0 + r)*QKV3n + h*64 + c4];
        *(uint4*)&Qs[r*68 + c4] = make_uint4(tf32_of(qv.x), tf32_of(qv.y), tf32_of(qv.z), tf32_of(qv.w));
    }

    float o[8][4];
    #pragma unroll
    for (int nt = 0; nt < 8; nt++)
        #pragma unroll
        for (int i = 0; i < 4; i++) o[nt][i] = 0.f;
    float mrow0 = -1e30f, mrow1 = -1e30f, lrow0 = 0.f, lrow1 = 0.f;

    const float* pr0 = pos + ((size_t)(h*Ln + i0 + m0 + g    ))*Ln;
    const float* pr1 = pos + ((size_t)(h*Ln + i0 + m0 + g + 8))*Ln;

    for (int jt = 0; jt < 16; jt++) {
        int j0 = jt * 64;
        __syncthreads();
        #pragma unroll
        for (int v = 0; v < 8; v++) {
            int f = tid + 128*v;
            int r = f >> 4, c4 = (f & 15) * 4;
            float4 kv = *(const float4*)&base[(size_t)(j0 + r)*QKV3n + INNERn + h*64 + c4];
            *(uint4*)&Ks[r*68 + c4] = make_uint4(tf32_of(kv.x), tf32_of(kv.y), tf32_of(kv.z), tf32_of(kv.w));
            float4 vv = *(const float4*)&base[(size_t)(j0 + r)*QKV3n + 2*INNERn + h*64 + c4];
            *(uint4*)&Vs[r*68 + c4] = make_uint4(tf32_of(vv.x), tf32_of(vv.y), tf32_of(vv.z), tf32_of(vv.w));
        }
        __syncthreads();

        float sa[8][4];
        #pragma unroll
        for (int nt = 0; nt < 8; nt++)
            #pragma unroll
            for (int i = 0; i < 4; i++) sa[nt][i] = 0.f;
        #pragma unroll
        for (int kc = 0; kc < 8; kc++) {
            int kb = kc * 8;
            unsigned a[4];
            a[0] = Qs[(m0 + g    )*68 + kb + t    ];
            a[1] = Qs[(m0 + g + 8)*68 + kb + t    ];
            a[2] = Qs[(m0 + g    )*68 + kb + t + 4];
            a[3] = Qs[(m0 + g + 8)*68 + kb + t + 4];
            #pragma unroll
            for (int nt = 0; nt < 8; nt++) {
                int n = nt*8 + g;
                unsigned bb[2];
                bb[0] = Ks[n*68 + kb + t    ];   // B[k][n] = K[n][k]
                bb[1] = Ks[n*68 + kb + t + 4];
                mma_tf32(sa[nt], a, bb);
            }
        }
        #pragma unroll
        for (int nt = 0; nt < 8; nt++) {
            float2 p0 = *(const float2*)&pr0[j0 + nt*8 + 2*t];
            float2 p1 = *(const float2*)&pr1[j0 + nt*8 + 2*t];
            sa[nt][0] = sa[nt][0]*0.125f + p0.x;
            sa[nt][1] = sa[nt][1]*0.125f + p0.y;
            sa[nt][2] = sa[nt][2]*0.125f + p1.x;
            sa[nt][3] = sa[nt][3]*0.125f + p1.y;
        }
        float mx0 = -1e30f, mx1 = -1e30f;
        #pragma unroll
        for (int nt = 0; nt < 8; nt++) {
            mx0 = fmaxf(mx0, fmaxf(sa[nt][0], sa[nt][1]));
            mx1 = fmaxf(mx1, fmaxf(sa[nt][2], sa[nt][3]));
        }
        mx0 = fmaxf(mx0, __shfl_xor_sync(0xffffffffu, mx0, 1));
        mx0 = fmaxf(mx0, __shfl_xor_sync(0xffffffffu, mx0, 2));
        mx1 = fmaxf(mx1, __shfl_xor_sync(0xffffffffu, mx1, 1));
        mx1 = fmaxf(mx1, __shfl_xor_sync(0xffffffffu, mx1, 2));
        float mn0 = fmaxf(mrow0, mx0), mn1 = fmaxf(mrow1, mx1);
        float corr0 = __expf(mrow0 - mn0), corr1 = __expf(mrow1 - mn1);
        float ts0 = 0.f, ts1 = 0.f;
        #pragma unroll
        for (int nt = 0; nt < 8; nt++) {
            float e0 = __expf(sa[nt][0] - mn0);
            float e1 = __expf(sa[nt][1] - mn0);
            float e2 = __expf(sa[nt][2] - mn1);
            float e3 = __expf(sa[nt][3] - mn1);
            ts0 += e0 + e1; ts1 += e2 + e3;
            int c = nt*8 + 2*t;
            *(uint2*)&Ps[(m0 + g    )*68 + c] = make_uint2(tf32_of(e0), tf32_of(e1));
            *(uint2*)&Ps[(m0 + g + 8)*68 + c] = make_uint2(tf32_of(e2), tf32_of(e3));
        }
        ts0 += __shfl_xor_sync(0xffffffffu, ts0, 1);
        ts0 += __shfl_xor_sync(0xffffffffu, ts0, 2);
        ts1 += __shfl_xor_sync(0xffffffffu, ts1, 1);
        ts1 += __shfl_xor_sync(0xffffffffu, ts1, 2);
        lrow0 = lrow0*corr0 + ts0;
        lrow1 = lrow1*corr1 + ts1;
        mrow0 = mn0; mrow1 = mn1;
        #pragma unroll
        for (int nt = 0; nt < 8; nt++) {
            o[nt][0] *= corr0; o[nt][1] *= corr0;
            o[nt][2] *= corr1; o[nt][3] *= corr1;
        }
        __syncwarp();
        #pragma unroll
        for (int kc = 0; kc < 8; kc++) {
            int kb = kc * 8;
            unsigned a[4];
            a[0] = Ps[(m0 + g    )*68 + kb + t    ];
            a[1] = Ps[(m0 + g + 8)*68 + kb + t    ];
            a[2] = Ps[(m0 + g    )*68 + kb + t + 4];
            a[3] = Ps[(m0 + g + 8)*68 + kb + t + 4];
            #pragma unroll
            for (int nt = 0; nt < 8; nt++) {
                unsigned bb[2];
                bb[0] = Vs[(kb + t    )*68 + nt*8 + g];
                bb[1] = Vs[(kb + t + 4)*68 + nt*8 + g];
                mma_tf32(o[nt], a, bb);
            }
        }
    }
    float inv0 = 1.f / lrow0, inv1 = 1.f / lrow1;
    size_t r0 = (size_t)b*Ln + i0 + m0 + g;
    size_t r1 = r0 + 8;
    #pragma unroll
    for (int nt = 0; nt < 8; nt++) {
        int col = h*64 + nt*8 + 2*t;
        *(float2*)&out[r0*INNERn + col] = make_float2(o[nt][0]*inv0, o[nt][1]*inv0);
        *(float2*)&out[r1*INNERn + col] = make_float2(o[nt][2]*inv1, o[nt][3]*inv1);
    }
}

// ---------------- SE pool tail ----------------
__global__ void se1_kernel(const float* __restrict__ wv, const float* __restrict__ w1,
                           const float* __restrict__ b1, float* __restrict__ t)
{
    int tid = threadIdx.x;                            // 512
    int b = tid >> 7, j = tid & 127;
    float acc = b1[j];
    for (int l = 0; l < Ln; l++) acc += wv[b*Ln + l] * w1[l*128 + j];
    t[tid] = fmaxf(acc, 0.f);
}

__global__ void se2_kernel(const float* __restrict__ t, const float* __restrict__ w2,
                           const float* __restrict__ b2, float* __restrict__ u)
{
    int idx = blockIdx.x * 256 + threadIdx.x;         // 4096
    int b = idx >> 10, l = idx & (Ln-1);
    float acc = b2[l];
    #pragma unroll
    for (int j = 0; j < 128; j++) acc += t[b*128 + j] * w2[j*Ln + l];
    u[idx] = 1.f / (1.f + __expf(-acc));
}

__global__ void pool_out_kernel(const float* __restrict__ u, const float* __restrict__ x,
                                float* __restrict__ out)
{
    int b = blockIdx.x, d = threadIdx.x;              // 4 x 256
    float acc = 0.f;
    for (int l = 0; l < Ln; l++) acc += u[b*Ln + l] * x[((size_t)b*Ln + l)*DIMn + d];
    out[b*DIMn + d] = acc;
}

// ---------------- host launch ----------------
extern "C" void kernel_launch(void* const* d_in, const int* in_sizes, int n_in,
                              void* d_out, int out_size)
{
    const float* img     = (const float*)d_in[0];
    const float* conv1_w = (const float*)d_in[1];
    const float* conv1_b = (const float*)d_in[2];
    const float* conv2_w = (const float*)d_in[3];
    const float* conv2_b = (const float*)d_in[4];
    const float* conv3_w = (const float*)d_in[5];
    const float* conv3_b = (const float*)d_in[6];
    const float* ln1_s   = (const float*)d_in[7];
    const float* ln1_b   = (const float*)d_in[8];
    const float* qkv_w   = (const float*)d_in[9];
    const float* pos     = (const float*)d_in[10];
    const float* out_w   = (const float*)d_in[11];
    const float* out_b   = (const float*)d_in[12];
    const float* ln2_s   = (const float*)d_in[13];
    const float* ln2_b   = (const float*)d_in[14];
    const float* ff_w1   = (const float*)d_in[15];
    const float* ff_b1   = (const float*)d_in[16];
    const float* ff_w2   = (const float*)d_in[17];
    const float* ff_b2   = (const float*)d_in[18];
    const float* se_w1   = (const float*)d_in[19];
    const float* se_b1   = (const float*)d_in[20];
    const float* se_w2   = (const float*)d_in[21];
    const float* se_b2   = (const float*)d_in[22];
    float* out = (float*)d_out;

    float *c1p, *c2p, *w2t, *w3t, *x, *qkv, *att, *mlp, *mstat, *rstat, *pw, *t, *u;
    cudaGetSymbolAddress((void**)&c1p, g_c1p);
    cudaGetSymbolAddress((void**)&c2p, g_c2p);
    cudaGetSymbolAddress((void**)&w2t, g_w2t);
    cudaGetSymbolAddress((void**)&w3t, g_w3t);
    cudaGetSymbolAddress((void**)&x,   g_x);
    cudaGetSymbolAddress((void**)&qkv, g_qkv);
    cudaGetSymbolAddress((void**)&att, g_att);
    cudaGetSymbolAddress((void**)&mlp, g_mlp);
    cudaGetSymbolAddress((void**)&mstat, g_m);
    cudaGetSymbolAddress((void**)&rstat, g_r);
    cudaGetSymbolAddress((void**)&pw,  g_pw);
    cudaGetSymbolAddress((void**)&t,   g_t);
    cudaGetSymbolAddress((void**)&u,   g_u);

    const int ATTN_SMEM = 4 * 64 * 68 * 4;                     // 69632 B
    const int GEMM_SMEM_128 = 2*(2*128*36 + 32*132) * 4;       // 107520 B
    const int GEMM_SMEM_64  = 2*(2*64*36  + 32*132) * 4;       // 70656 B
    cudaFuncSetAttribute(attn_kernel, cudaFuncAttributeMaxDynamicSharedMemorySize, ATTN_SMEM);
    cudaFuncSetAttribute(gemm_tf32_kernel<128,false,false,false,true>,
                         cudaFuncAttributeMaxDynamicSharedMemorySize, GEMM_SMEM_128);
    cudaFuncSetAttribute(gemm_tf32_kernel<128,true,true,false,true>,
                         cudaFuncAttributeMaxDynamicSharedMemorySize, GEMM_SMEM_128);
    cudaFuncSetAttribute(gemm_tf32_kernel<64,false,true,true,false>,
                         cudaFuncAttributeMaxDynamicSharedMemorySize, GEMM_SMEM_64);
    cudaFuncSetAttribute(conv_gemm_kernel<false>,
                         cudaFuncAttributeMaxDynamicSharedMemorySize, GEMM_SMEM_64);
    cudaFuncSetAttribute(conv_gemm_kernel<true>,
                         cudaFuncAttributeMaxDynamicSharedMemorySize, GEMM_SMEM_64);

    // conv patch embed
    conv1_kernel<<<(Bn*256*2*Ln + 255)/256, 256>>>(img, conv1_w, conv1_b, c1p);
    pad_zero_kernel<<<(2048*8 + 1024*8 + 255)/256, 256>>>(c1p, c2p);
    wtrans_kernel<<<(256*1536 + 255)/256, 256>>>(conv2_w, w2t, 512, 256*1536);
    wtrans_kernel<<<(256*768  + 255)/256, 256>>>(conv3_w, w3t, 256, 256*768);
    conv_gemm_kernel<false><<<dim3(8, 4, Bn), 256, GEMM_SMEM_64>>>(w2t, c1p, conv2_b, c2p, 1536, 512, 9);
    conv_gemm_kernel<true ><<<dim3(8, 4, Bn), 256, GEMM_SMEM_64>>>(w3t, c2p, conv3_b, x,   768,  256, 8);

    for (int lyr = 0; lyr < DEPTHn; lyr++) {
        // attention block (LN fused into qkv A-staging)
        rowstat_kernel<<<ROWS/8, 256>>>(x, mstat, rstat);
        gemm_tf32_kernel<128,false,false,false,true><<<dim3(QKV3n/128, ROWS/128), 256, GEMM_SMEM_128>>>(
            x, qkv_w + (size_t)lyr*DIMn*QKV3n, nullptr, nullptr, qkv, ROWS, QKV3n, DIMn,
            mstat, rstat, ln1_s + lyr*DIMn, ln1_b + lyr*DIMn);
        attn_kernel<<<dim3(Ln/64, HEADSn, Bn), 128, ATTN_SMEM>>>(
            qkv, pos + (size_t)lyr*HEADSn*Ln*Ln, att);
        gemm_tf32_kernel<64,false,true,true,false><<<dim3(DIMn/128, ROWS/64), 256, GEMM_SMEM_64>>>(
            att, out_w + (size_t)lyr*INNERn*DIMn, out_b + lyr*DIMn, x, x, ROWS, DIMn, INNERn,
            nullptr, nullptr, nullptr, nullptr);
        // MLP block (LN fused into ff1 A-staging)
        rowstat_kernel<<<ROWS/8, 256>>>(x, mstat, rstat);
        gemm_tf32_kernel<128,true,true,false,true><<<dim3(MLPn/128, ROWS/128), 256, GEMM_SMEM_128>>>(
            x, ff_w1 + (size_t)lyr*DIMn*MLPn, ff_b1 + lyr*MLPn, nullptr, mlp, ROWS, MLPn, DIMn,
            mstat, rstat, ln2_s + lyr*DIMn, ln2_b + lyr*DIMn);
        gemm_tf32_kernel<64,false,true,true,false><<<dim3(DIMn/128, ROWS/64), 256, GEMM_SMEM_64>>>(
            mlp, ff_w2 + (size_t)lyr*MLPn*DIMn, ff_b2 + lyr*DIMn, x, x, ROWS, DIMn, MLPn,
            nullptr, nullptr, nullptr, nullptr);
    }

    // SE attention pool
    meanpool_kernel<<<ROWS/8, 256>>>(x, pw);
    se1_kernel<<<1, 512>>>(pw, se_w1, se_b1, t);
    se2_kernel<<<(Bn*Ln)/256, 256>>>(t, se_w2, se_b2, u);
    pool_out_kernel<<<Bn, 256>>>(u, x, out);
}